// round 1
// baseline (speedup 1.0000x reference)
#include <cuda_runtime.h>

// Problem constants
#define BB   4
#define CC   256
#define HH   64
#define WW   64
#define HWP  4096            // H*W
#define NP   16384           // B*H*W total pixels
#define NH   4
#define NQ   16
#define HD   64
#define RG   320             // 64 attn rows + 256 u rows
#define YC   1024            // NQ*HD

// ---------------- scratch (static device memory; no allocation) -------------
__device__ __align__(16) float g_Wc[RG * CC];        // combined projection weight
__device__ float g_zb[CC];                            // combined output bias
__device__ __align__(16) float g_G[(size_t)NP * RG];  // per-pixel [attn(64) | u(256)]
__device__ __align__(16) float g_Y[(size_t)NP * YC];  // per-pixel y (pixel-major)

// ---------------- 0. fold weights: Wc = f(dot_w, head_w, kv_w), zb ----------
// rows 0..63   : attnW[n*16+q][c] = sum_d dot_w[n,q,d] * kv_w[n*64+d][c]
// rows 64..319 : uW[n*64+o][c]    = sum_d head_w[o][n*64+d] * kv_w[256+n*64+d][c]
__global__ void precompute_kernel(const float* __restrict__ kv_w,
                                  const float* __restrict__ dot_w,
                                  const float* __restrict__ head_w,
                                  const float* __restrict__ head_b,
                                  const float* __restrict__ q_w,
                                  const float* __restrict__ q_b) {
    int r = blockIdx.x;     // 0..319
    int c = threadIdx.x;    // 0..255
    float acc = 0.f;
    if (r < 64) {
        int n = r >> 4;
        const float* dw = dot_w + r * 64;                 // dot_w[n][q][:]
        const float* kw = kv_w + (n * 64) * CC + c;
        #pragma unroll 8
        for (int d = 0; d < 64; d++) acc += dw[d] * kw[d * CC];
    } else {
        int t = r - 64;
        int n = t >> 6, o = t & 63;
        const float* hw_ = head_w + o * CC + n * 64;      // head_w[o][n*64+d]
        const float* kw  = kv_w + (256 + n * 64) * CC + c;
        #pragma unroll 8
        for (int d = 0; d < 64; d++) acc += hw_[d] * kw[d * CC];
    }
    g_Wc[r * CC + c] = acc;
    // combined bias: zb[oc] = q_b[oc] + sum_ch q_w[oc][ch]*head_b[ch%64]
    if (r == 0) {
        float bacc = q_b[c];
        for (int ch = 0; ch < YC; ch++) bacc += q_w[c * YC + ch] * head_b[ch & 63];
        g_zb[c] = bacc;
    }
}

// ---------------- 1. GEMM: G[P][r] = sum_c Wc[r][c] * x[b,c,hw] -------------
// M=320 (5 tiles of 64), K=256, N=16384 (256 tiles of 64). Output pixel-major.
__global__ __launch_bounds__(256) void gemm_G(const float* __restrict__ x) {
    __shared__ float As[16][68];   // stride 272B = 17*16B -> float4-aligned rows
    __shared__ float Bs[16][68];
    const int mt = blockIdx.y;                 // 0..4
    const int P0 = blockIdx.x << 6;            // pixel tile base
    const int b  = P0 >> 12;
    const float* xb  = x + (size_t)b * (CC * HWP) + (P0 & 4095);
    const float* Wcm = g_Wc + mt * 64 * CC;
    const int tid = threadIdx.x;
    const int tx = tid & 15, ty = tid >> 4;
    float acc[4][4] = {};
    for (int kk = 0; kk < CC; kk += 16) {
        #pragma unroll
        for (int i = 0; i < 4; i++) {
            int idx = tid + (i << 8);
            int m = idx >> 4, k = idx & 15;
            As[k][m] = Wcm[m * CC + kk + k];
        }
        #pragma unroll
        for (int i = 0; i < 4; i++) {
            int idx = tid + (i << 8);
            int k = idx >> 6, p = idx & 63;
            Bs[k][p] = xb[(kk + k) * HWP + p];
        }
        __syncthreads();
        #pragma unroll
        for (int k = 0; k < 16; k++) {
            float4 a4 = *(const float4*)&As[k][ty << 2];
            float4 b4 = *(const float4*)&Bs[k][tx << 2];
            float a[4] = {a4.x, a4.y, a4.z, a4.w};
            float bv[4] = {b4.x, b4.y, b4.z, b4.w};
            #pragma unroll
            for (int i = 0; i < 4; i++)
                #pragma unroll
                for (int j = 0; j < 4; j++) acc[i][j] += a[i] * bv[j];
        }
        __syncthreads();
    }
    #pragma unroll
    for (int j = 0; j < 4; j++) {
        int P = P0 + (tx << 2) + j;
        float* gp = g_G + (size_t)P * RG + mt * 64 + (ty << 2);
        #pragma unroll
        for (int i = 0; i < 4; i++) gp[i] = acc[i][j];
    }
}

// ---------------- 2. fused window softmax + apply ---------------------------
// Per pixel: gather 9-neighborhood of [attn|u], softmax attn over window
// (zero-padded OOB values INCLUDED in softmax, matching reference unfold+pad),
// y[q*64+o] = sum_{n,l} A[n,q,l] * u[n,o, nbr_l]  (OOB u = 0).
__global__ __launch_bounds__(128) void attn_kernel() {
    const int P  = blockIdx.x;
    const int b  = P >> 12;
    const int hw = P & 4095;
    const int h = hw >> 6, w = hw & 63;
    __shared__ float attn_s[9][64];
    __shared__ float u_s[9][256];
    __shared__ float A_s[64][10];
    const int tid = threadIdx.x;

    // load 9 neighbors x 320 floats = 720 float4's
    for (int idx = tid; idx < 9 * 80; idx += 128) {
        int l  = idx / 80;
        int r4 = idx - l * 80;
        int hh = h + l / 3 - 1;
        int ww = w + l % 3 - 1;
        float4 v = make_float4(0.f, 0.f, 0.f, 0.f);
        if ((unsigned)hh < 64u && (unsigned)ww < 64u) {
            const float4* src = (const float4*)(g_G + (size_t)((b << 12) + (hh << 6) + ww) * RG);
            v = src[r4];
        }
        int r = r4 << 2;
        if (r < 64) {
            attn_s[l][r] = v.x; attn_s[l][r + 1] = v.y;
            attn_s[l][r + 2] = v.z; attn_s[l][r + 3] = v.w;
        } else {
            int rr = r - 64;
            u_s[l][rr] = v.x; u_s[l][rr + 1] = v.y;
            u_s[l][rr + 2] = v.z; u_s[l][rr + 3] = v.w;
        }
    }
    __syncthreads();

    // softmax over l for each of the 64 (n,q) pairs
    if (tid < 64) {
        float m = attn_s[0][tid];
        #pragma unroll
        for (int l = 1; l < 9; l++) m = fmaxf(m, attn_s[l][tid]);
        float e[9], s = 0.f;
        #pragma unroll
        for (int l = 0; l < 9; l++) { e[l] = __expf(attn_s[l][tid] - m); s += e[l]; }
        float inv = 1.f / s;
        #pragma unroll
        for (int l = 0; l < 9; l++) A_s[tid][l] = e[l] * inv;
    }
    __syncthreads();

    // each thread: fixed o = tid&63, q in {tid>>6 + 2*ii}; u cached in regs
    const int o  = tid & 63;
    const int qb = tid >> 6;
    float ur[4][9];
    #pragma unroll
    for (int n = 0; n < 4; n++)
        #pragma unroll
        for (int l = 0; l < 9; l++) ur[n][l] = u_s[l][n * 64 + o];

    float* yout = g_Y + (size_t)P * YC;
    #pragma unroll
    for (int ii = 0; ii < 8; ii++) {
        int q = qb + (ii << 1);
        float acc = 0.f;
        #pragma unroll
        for (int n = 0; n < 4; n++)
            #pragma unroll
            for (int l = 0; l < 9; l++) acc += A_s[n * 16 + q][l] * ur[n][l];
        yout[(q << 6) + o] = acc;
    }
}

// ---------------- 3. GEMM: z[oc][P] = sum_ch q_w[oc][ch]*Y[P][ch] + zb ------
// M=256 (4 tiles), K=1024, N=16384 (256 tiles).
__global__ __launch_bounds__(256) void gemm_Z(const float* __restrict__ qw,
                                              float* __restrict__ out) {
    __shared__ float As[16][68];
    __shared__ float Bs[16][68];
    const int mt = blockIdx.y;                 // 0..3
    const int P0 = blockIdx.x << 6;
    const float* Arow  = qw + mt * 64 * YC;
    const float* Bbase = g_Y + (size_t)P0 * YC;
    const int tid = threadIdx.x;
    const int tx = tid & 15, ty = tid >> 4;
    float acc[4][4] = {};
    for (int kk = 0; kk < YC; kk += 16) {
        #pragma unroll
        for (int i = 0; i < 4; i++) {
            int idx = tid + (i << 8);
            int m = idx >> 4, k = idx & 15;
            As[k][m] = Arow[m * YC + kk + k];
        }
        #pragma unroll
        for (int i = 0; i < 4; i++) {
            int idx = tid + (i << 8);
            int p = idx >> 4, k = idx & 15;
            Bs[k][p] = Bbase[(size_t)p * YC + kk + k];
        }
        __syncthreads();
        #pragma unroll
        for (int k = 0; k < 16; k++) {
            float4 a4 = *(const float4*)&As[k][ty << 2];
            float4 b4 = *(const float4*)&Bs[k][tx << 2];
            float a[4] = {a4.x, a4.y, a4.z, a4.w};
            float bv[4] = {b4.x, b4.y, b4.z, b4.w};
            #pragma unroll
            for (int i = 0; i < 4; i++)
                #pragma unroll
                for (int j = 0; j < 4; j++) acc[i][j] += a[i] * bv[j];
        }
        __syncthreads();
    }
    const int b   = P0 >> 12;
    const int hw0 = (P0 & 4095) + (tx << 2);
    #pragma unroll
    for (int i = 0; i < 4; i++) {
        int oc = mt * 64 + (ty << 2) + i;
        float bias = g_zb[oc];
        float* op = out + (size_t)b * (CC * HWP) + (size_t)oc * HWP + hw0;
        #pragma unroll
        for (int j = 0; j < 4; j++) op[j] = acc[i][j] + bias;
    }
}

// ---------------- launcher ---------------------------------------------------
extern "C" void kernel_launch(void* const* d_in, const int* in_sizes, int n_in,
                              void* d_out, int out_size) {
    const float* x      = (const float*)d_in[0];
    const float* kv_w   = (const float*)d_in[1];
    const float* dot_w  = (const float*)d_in[2];
    const float* head_w = (const float*)d_in[3];
    const float* head_b = (const float*)d_in[4];
    const float* q_w    = (const float*)d_in[5];
    const float* q_b    = (const float*)d_in[6];
    float* out = (float*)d_out;

    precompute_kernel<<<RG, CC>>>(kv_w, dot_w, head_w, head_b, q_w, q_b);
    gemm_G<<<dim3(NP / 64, RG / 64), 256>>>(x);
    attn_kernel<<<NP, 128>>>();
    gemm_Z<<<dim3(NP / 64, CC / 64), 256>>>(q_w, out);
}

// round 3
// speedup vs baseline: 1.4224x; 1.4224x over previous
#include <cuda_runtime.h>
#include <cuda_bf16.h>
#include <stdint.h>

#define CC   256
#define HWP  4096
#define NP   16384
#define RGP  384          // padded combined rows (320 used: 64 attn + 256 u)
#define YC   1024

// ---------------- static device scratch ------------------------------------
__device__ __align__(16) __nv_bfloat16 g_Wch[RGP * CC];
__device__ __align__(16) __nv_bfloat16 g_Wcl[RGP * CC];
__device__ float g_zb[CC];
__device__ __align__(16) __nv_bfloat16 g_qwh[CC * YC];
__device__ __align__(16) __nv_bfloat16 g_qwl[CC * YC];
__device__ __align__(16) __nv_bfloat16 g_xth[(size_t)NP * CC];
__device__ __align__(16) __nv_bfloat16 g_xtl[(size_t)NP * CC];
__device__ __align__(16) float g_G[(size_t)NP * RGP];
__device__ __align__(16) __nv_bfloat16 g_Yh[(size_t)NP * YC];
__device__ __align__(16) __nv_bfloat16 g_Yl[(size_t)NP * YC];

// ---------------- warp-MMA helpers (target-neutral PTX, sm_80+) -------------
__device__ __forceinline__ uint32_t smem_u32(const void* p) {
    uint32_t a;
    asm("{ .reg .u64 t; cvta.to.shared.u64 t, %1; cvt.u32.u64 %0, t; }" : "=r"(a) : "l"(p));
    return a;
}
__device__ __forceinline__ void ldsm4(uint32_t* r, uint32_t a) {
    asm volatile("ldmatrix.sync.aligned.m8n8.x4.shared.b16 {%0,%1,%2,%3}, [%4];"
        : "=r"(r[0]), "=r"(r[1]), "=r"(r[2]), "=r"(r[3]) : "r"(a));
}
__device__ __forceinline__ void ldsm2(uint32_t* r, uint32_t a) {
    asm volatile("ldmatrix.sync.aligned.m8n8.x2.shared.b16 {%0,%1}, [%2];"
        : "=r"(r[0]), "=r"(r[1]) : "r"(a));
}
__device__ __forceinline__ void mma16816(float* c, const uint32_t* a, const uint32_t* b) {
    asm volatile(
        "mma.sync.aligned.m16n8k16.row.col.f32.bf16.bf16.f32 "
        "{%0,%1,%2,%3}, {%4,%5,%6,%7}, {%8,%9}, {%0,%1,%2,%3};"
        : "+f"(c[0]), "+f"(c[1]), "+f"(c[2]), "+f"(c[3])
        : "r"(a[0]), "r"(a[1]), "r"(a[2]), "r"(a[3]), "r"(b[0]), "r"(b[1]));
}

// smem: 4 bf16 tiles of 128 rows x 64 halves, padded stride 144B (72 halves)
#define SM_STRIDE 144
#define OFF_AH 0
#define OFF_AL 18432
#define OFF_BH 36864
#define OFF_BL 55296
#define SMEM_BYTES 73728

// ---------------- 0a. fold weights + split to bf16 hi/lo --------------------
__global__ void precompute_kernel(const float* __restrict__ kv_w,
                                  const float* __restrict__ dot_w,
                                  const float* __restrict__ head_w,
                                  const float* __restrict__ head_b,
                                  const float* __restrict__ q_w,
                                  const float* __restrict__ q_b) {
    int r = blockIdx.x;     // 0..383
    int c = threadIdx.x;    // 0..255
    float acc = 0.f;
    if (r < 64) {
        int n = r >> 4;
        const float* dw = dot_w + r * 64;
        const float* kw = kv_w + (n * 64) * CC + c;
        #pragma unroll 8
        for (int d = 0; d < 64; d++) acc += dw[d] * kw[d * CC];
    } else if (r < 320) {
        int t = r - 64;
        int n = t >> 6, o = t & 63;
        const float* hw_ = head_w + o * CC + n * 64;
        const float* kw  = kv_w + (256 + n * 64) * CC + c;
        #pragma unroll 8
        for (int d = 0; d < 64; d++) acc += hw_[d] * kw[d * CC];
    }
    __nv_bfloat16 hi = __float2bfloat16(acc);
    g_Wch[r * CC + c] = hi;
    g_Wcl[r * CC + c] = __float2bfloat16(acc - __bfloat162float(hi));
    if (r == 0) {
        float bacc = q_b[c];
        for (int ch = 0; ch < YC; ch++) bacc += q_w[c * YC + ch] * head_b[ch & 63];
        g_zb[c] = bacc;
    }
}

// ---------------- 0b. split q_w to bf16 hi/lo --------------------------------
__global__ void convert_qw(const float* __restrict__ q_w) {
    int i = blockIdx.x * 512 + threadIdx.x;
    if (i < CC * YC) {
        float v = q_w[i];
        __nv_bfloat16 hi = __float2bfloat16(v);
        g_qwh[i] = hi;
        g_qwl[i] = __float2bfloat16(v - __bfloat162float(hi));
    }
}

// ---------------- 0c. transpose + split x: xt[P][c] bf16 hi/lo --------------
__global__ void transpose_split_x(const float* __restrict__ x) {
    __shared__ float s[32][33];
    const int bx = blockIdx.x;   // hw tile
    const int by = blockIdx.y;   // c tile
    const int b  = blockIdx.z;
    const int tx = threadIdx.x, ty = threadIdx.y;
    const float* xb = x + ((size_t)b * CC + by * 32) * HWP + bx * 32;
    #pragma unroll
    for (int i = 0; i < 4; i++)
        s[ty + i * 8][tx] = xb[(size_t)(ty + i * 8) * HWP + tx];
    __syncthreads();
    #pragma unroll
    for (int i = 0; i < 4; i++) {
        int hw = bx * 32 + ty + i * 8;
        int c  = by * 32 + tx;
        float v = s[tx][ty + i * 8];
        size_t o = ((size_t)(b * HWP + hw)) * CC + c;
        __nv_bfloat16 hi = __float2bfloat16(v);
        g_xth[o] = hi;
        g_xtl[o] = __float2bfloat16(v - __bfloat162float(hi));
    }
}

// ---------------- 1+3. warp-MMA GEMM (split-bf16, 3 products) ---------------
// C[M,N] = A[M,KTOT] . B[N,KTOT]^T ; CTA tile 128x128, 8 warps of 64x32.
// ZOUT=true:  out[b][oc][hw] += zb bias (gemm_Z)
// ZOUT=false: g_G[P][RGP] transposed store (gemm_G)
template<int KTOT, bool ZOUT>
__global__ __launch_bounds__(256) void gemm_mma(
    const __nv_bfloat16* __restrict__ Ah_g, const __nv_bfloat16* __restrict__ Al_g,
    const __nv_bfloat16* __restrict__ Bh_g, const __nv_bfloat16* __restrict__ Bl_g,
    float* __restrict__ outp)
{
    extern __shared__ __align__(16) char sm[];
    const uint32_t smb = smem_u32(sm);
    const int tid  = threadIdx.x;
    const int lane = tid & 31, wid = tid >> 5;
    const int wm = wid >> 2, wn = wid & 3;
    const int mt = blockIdx.y;
    const int P0 = blockIdx.x << 7;

    const __nv_bfloat16* Ah = Ah_g + (size_t)(mt * 128) * KTOT;
    const __nv_bfloat16* Al = Al_g + (size_t)(mt * 128) * KTOT;
    const __nv_bfloat16* Bh = Bh_g + (size_t)P0 * KTOT;
    const __nv_bfloat16* Bl = Bl_g + (size_t)P0 * KTOT;

    float c[4][4][4];
    #pragma unroll
    for (int i = 0; i < 4; i++)
        #pragma unroll
        for (int j = 0; j < 4; j++)
            #pragma unroll
            for (int k = 0; k < 4; k++) c[i][j][k] = 0.f;

    for (int kc = 0; kc < KTOT / 64; kc++) {
        const int kb = kc * 64;
        #pragma unroll
        for (int i = 0; i < 4; i++) {
            int idx = tid + (i << 8);
            int row = idx >> 3, c16 = idx & 7;
            size_t   go = (size_t)row * KTOT + kb + c16 * 8;
            uint32_t so = row * SM_STRIDE + c16 * 16;
            *(uint4*)(sm + OFF_AH + so) = *(const uint4*)(Ah + go);
            *(uint4*)(sm + OFF_AL + so) = *(const uint4*)(Al + go);
            *(uint4*)(sm + OFF_BH + so) = *(const uint4*)(Bh + go);
            *(uint4*)(sm + OFF_BL + so) = *(const uint4*)(Bl + go);
        }
        __syncthreads();
        #pragma unroll
        for (int ks = 0; ks < 4; ks++) {
            const int k0 = ks * 16;
            uint32_t bhf[4][2], blf[4][2];
            #pragma unroll
            for (int j = 0; j < 4; j++) {
                uint32_t brow = wn * 32 + j * 8 + (lane & 7);
                uint32_t bcol = k0 + ((lane >> 3) & 1) * 8;
                uint32_t a = smb + OFF_BH + brow * SM_STRIDE + bcol * 2;
                ldsm2(bhf[j], a);
                ldsm2(blf[j], a + (OFF_BL - OFF_BH));
            }
            #pragma unroll
            for (int i = 0; i < 4; i++) {
                uint32_t ahf[4], alf[4];
                uint32_t arow = wm * 64 + i * 16 + (lane & 15);
                uint32_t acol = k0 + (lane >> 4) * 8;
                uint32_t a = smb + OFF_AH + arow * SM_STRIDE + acol * 2;
                ldsm4(ahf, a);
                ldsm4(alf, a + (OFF_AL - OFF_AH));
                #pragma unroll
                for (int j = 0; j < 4; j++) {
                    mma16816(c[i][j], ahf, bhf[j]);
                    mma16816(c[i][j], ahf, blf[j]);
                    mma16816(c[i][j], alf, bhf[j]);
                }
            }
        }
        __syncthreads();
    }

    // epilogue via SMEM (reuse tile buffers)
    float* Cs = (float*)sm;
    #pragma unroll
    for (int i = 0; i < 4; i++)
        #pragma unroll
        for (int j = 0; j < 4; j++) {
            int r0 = wm * 64 + i * 16 + (lane >> 2);
            int nc = wn * 32 + j * 8 + (lane & 3) * 2;
            if (ZOUT) {
                Cs[r0 * 132 + nc]           = c[i][j][0];
                Cs[r0 * 132 + nc + 1]       = c[i][j][1];
                Cs[(r0 + 8) * 132 + nc]     = c[i][j][2];
                Cs[(r0 + 8) * 132 + nc + 1] = c[i][j][3];
            } else {
                Cs[nc * 132 + r0]           = c[i][j][0];
                Cs[(nc + 1) * 132 + r0]     = c[i][j][1];
                Cs[nc * 132 + r0 + 8]       = c[i][j][2];
                Cs[(nc + 1) * 132 + r0 + 8] = c[i][j][3];
            }
        }
    __syncthreads();
    if (ZOUT) {
        const int b = P0 >> 12, hw0 = P0 & 4095;
        float* ob = outp + (size_t)b * CC * HWP + hw0;
        #pragma unroll
        for (int s = 0; s < 16; s++) {
            int m  = s * 8 + wid;
            int oc = mt * 128 + m;
            float bias = g_zb[oc];
            float4 v = *(float4*)&Cs[m * 132 + lane * 4];
            v.x += bias; v.y += bias; v.z += bias; v.w += bias;
            *(float4*)(ob + (size_t)oc * HWP + lane * 4) = v;
        }
    } else {
        #pragma unroll
        for (int s = 0; s < 16; s++) {
            int p = s * 8 + wid;
            float4 v = *(float4*)&Cs[p * 132 + lane * 4];
            *(float4*)(g_G + (size_t)(P0 + p) * RGP + mt * 128 + lane * 4) = v;
        }
    }
}

// ---------------- 2. fused window softmax + apply (2 pixels / CTA) ----------
__global__ __launch_bounds__(256) void attn_kernel() {
    __shared__ float attn_s[2][9][64];
    __shared__ float u_s[2][9][256];
    __shared__ float A_s[2][64][10];
    const int sub = threadIdx.x >> 7;
    const int t   = threadIdx.x & 127;
    const int P   = blockIdx.x * 2 + sub;
    const int b   = P >> 12;
    const int hw  = P & 4095;
    const int h = hw >> 6, w = hw & 63;

    for (int idx = t; idx < 720; idx += 128) {
        int l  = idx / 80;
        int r4 = idx - l * 80;
        int hh = h + l / 3 - 1;
        int ww = w + l % 3 - 1;
        float4 v = make_float4(0.f, 0.f, 0.f, 0.f);
        if ((unsigned)hh < 64u && (unsigned)ww < 64u)
            v = ((const float4*)(g_G + (size_t)((b << 12) + (hh << 6) + ww) * RGP))[r4];
        int r = r4 << 2;
        if (r < 64) {
            attn_s[sub][l][r] = v.x; attn_s[sub][l][r + 1] = v.y;
            attn_s[sub][l][r + 2] = v.z; attn_s[sub][l][r + 3] = v.w;
        } else {
            int rr = r - 64;
            u_s[sub][l][rr] = v.x; u_s[sub][l][rr + 1] = v.y;
            u_s[sub][l][rr + 2] = v.z; u_s[sub][l][rr + 3] = v.w;
        }
    }
    __syncthreads();
    if (t < 64) {
        float m = attn_s[sub][0][t];
        #pragma unroll
        for (int l = 1; l < 9; l++) m = fmaxf(m, attn_s[sub][l][t]);
        float e[9], s = 0.f;
        #pragma unroll
        for (int l = 0; l < 9; l++) { e[l] = __expf(attn_s[sub][l][t] - m); s += e[l]; }
        float inv = 1.f / s;
        #pragma unroll
        for (int l = 0; l < 9; l++) A_s[sub][t][l] = e[l] * inv;
    }
    __syncthreads();

    const int o  = t & 63;
    const int qb = t >> 6;
    float ur[4][9];
    #pragma unroll
    for (int n = 0; n < 4; n++)
        #pragma unroll
        for (int l = 0; l < 9; l++) ur[n][l] = u_s[sub][l][n * 64 + o];

    const size_t base = (size_t)P * YC;
    #pragma unroll
    for (int ii = 0; ii < 8; ii++) {
        int q = qb + (ii << 1);
        float acc = 0.f;
        #pragma unroll
        for (int n = 0; n < 4; n++)
            #pragma unroll
            for (int l = 0; l < 9; l++) acc += A_s[sub][n * 16 + q][l] * ur[n][l];
        __nv_bfloat16 hi = __float2bfloat16(acc);
        g_Yh[base + (q << 6) + o] = hi;
        g_Yl[base + (q << 6) + o] = __float2bfloat16(acc - __bfloat162float(hi));
    }
}

// ---------------- launcher ---------------------------------------------------
extern "C" void kernel_launch(void* const* d_in, const int* in_sizes, int n_in,
                              void* d_out, int out_size) {
    const float* x      = (const float*)d_in[0];
    const float* kv_w   = (const float*)d_in[1];
    const float* dot_w  = (const float*)d_in[2];
    const float* head_w = (const float*)d_in[3];
    const float* head_b = (const float*)d_in[4];
    const float* q_w    = (const float*)d_in[5];
    const float* q_b    = (const float*)d_in[6];
    float* out = (float*)d_out;

    cudaFuncSetAttribute(gemm_mma<256,  false>, cudaFuncAttributeMaxDynamicSharedMemorySize, SMEM_BYTES);
    cudaFuncSetAttribute(gemm_mma<1024, true >, cudaFuncAttributeMaxDynamicSharedMemorySize, SMEM_BYTES);

    precompute_kernel<<<RGP, CC>>>(kv_w, dot_w, head_w, head_b, q_w, q_b);
    convert_qw<<<(CC * YC + 511) / 512, 512>>>(q_w);
    transpose_split_x<<<dim3(HWP / 32, CC / 32, 4), dim3(32, 8)>>>(x);

    __nv_bfloat16 *wch, *wcl, *xth, *xtl, *qwh, *qwl, *yh, *yl;
    cudaGetSymbolAddress((void**)&wch, g_Wch);
    cudaGetSymbolAddress((void**)&wcl, g_Wcl);
    cudaGetSymbolAddress((void**)&xth, g_xth);
    cudaGetSymbolAddress((void**)&xtl, g_xtl);
    cudaGetSymbolAddress((void**)&qwh, g_qwh);
    cudaGetSymbolAddress((void**)&qwl, g_qwl);
    cudaGetSymbolAddress((void**)&yh, g_Yh);
    cudaGetSymbolAddress((void**)&yl, g_Yl);

    gemm_mma<256, false><<<dim3(NP / 128, 3), 256, SMEM_BYTES>>>(wch, wcl, xth, xtl, nullptr);
    attn_kernel<<<NP / 2, 256>>>();
    gemm_mma<1024, true><<<dim3(NP / 128, 2), 256, SMEM_BYTES>>>(qwh, qwl, yh, yl, out);
}

// round 4
// speedup vs baseline: 1.5833x; 1.1132x over previous
#include <cuda_runtime.h>
#include <cuda_bf16.h>
#include <stdint.h>

#define CC   256
#define HWP  4096
#define NP   16384
#define RGP  384          // padded combined rows (320 used: 64 attn + 256 u)
#define YC   1024

// ---------------- static device scratch ------------------------------------
__device__ __align__(16) __nv_bfloat16 g_Wch[RGP * CC];
__device__ __align__(16) __nv_bfloat16 g_Wcl[RGP * CC];
__device__ float g_zb[CC];
__device__ __align__(16) __nv_bfloat16 g_qwh[CC * YC];
__device__ __align__(16) __nv_bfloat16 g_qwl[CC * YC];
__device__ __align__(16) __nv_bfloat16 g_xth[(size_t)NP * CC];
__device__ __align__(16) __nv_bfloat16 g_xtl[(size_t)NP * CC];
__device__ __align__(16) float g_G[(size_t)NP * RGP];
__device__ __align__(16) __nv_bfloat16 g_Yh[(size_t)NP * YC];
__device__ __align__(16) __nv_bfloat16 g_Yl[(size_t)NP * YC];

// ---------------- warp-MMA helpers (target-neutral PTX, sm_80+) -------------
__device__ __forceinline__ uint32_t smem_u32(const void* p) {
    uint32_t a;
    asm("{ .reg .u64 t; cvta.to.shared.u64 t, %1; cvt.u32.u64 %0, t; }" : "=r"(a) : "l"(p));
    return a;
}
__device__ __forceinline__ void ldsm4(uint32_t* r, uint32_t a) {
    asm volatile("ldmatrix.sync.aligned.m8n8.x4.shared.b16 {%0,%1,%2,%3}, [%4];"
        : "=r"(r[0]), "=r"(r[1]), "=r"(r[2]), "=r"(r[3]) : "r"(a));
}
__device__ __forceinline__ void ldsm2(uint32_t* r, uint32_t a) {
    asm volatile("ldmatrix.sync.aligned.m8n8.x2.shared.b16 {%0,%1}, [%2];"
        : "=r"(r[0]), "=r"(r[1]) : "r"(a));
}
__device__ __forceinline__ void mma16816(float* c, const uint32_t* a, const uint32_t* b) {
    asm volatile(
        "mma.sync.aligned.m16n8k16.row.col.f32.bf16.bf16.f32 "
        "{%0,%1,%2,%3}, {%4,%5,%6,%7}, {%8,%9}, {%0,%1,%2,%3};"
        : "+f"(c[0]), "+f"(c[1]), "+f"(c[2]), "+f"(c[3])
        : "r"(a[0]), "r"(a[1]), "r"(a[2]), "r"(a[3]), "r"(b[0]), "r"(b[1]));
}
__device__ __forceinline__ void cp16(uint32_t s, const void* g) {
    asm volatile("cp.async.cg.shared.global [%0], [%1], 16;" :: "r"(s), "l"(g) : "memory");
}

// smem per stage: 4 bf16 tiles of 128 rows x 64 halves, padded stride 144B
#define SM_STRIDE 144
#define OFF_AH 0
#define OFF_AL 18432
#define OFF_BH 36864
#define OFF_BL 55296
#define STAGE_BYTES 73728
#define SMEM_BYTES (2 * STAGE_BYTES)   // 147456

// ---------------- 0a. fold weights + split to bf16 hi/lo --------------------
__global__ void precompute_kernel(const float* __restrict__ kv_w,
                                  const float* __restrict__ dot_w,
                                  const float* __restrict__ head_w,
                                  const float* __restrict__ head_b,
                                  const float* __restrict__ q_w,
                                  const float* __restrict__ q_b) {
    int r = blockIdx.x;     // 0..383
    int c = threadIdx.x;    // 0..255
    float acc = 0.f;
    if (r < 64) {
        int n = r >> 4;
        const float* dw = dot_w + r * 64;
        const float* kw = kv_w + (n * 64) * CC + c;
        #pragma unroll 8
        for (int d = 0; d < 64; d++) acc += dw[d] * kw[d * CC];
    } else if (r < 320) {
        int t = r - 64;
        int n = t >> 6, o = t & 63;
        const float* hw_ = head_w + o * CC + n * 64;
        const float* kw  = kv_w + (256 + n * 64) * CC + c;
        #pragma unroll 8
        for (int d = 0; d < 64; d++) acc += hw_[d] * kw[d * CC];
    }
    __nv_bfloat16 hi = __float2bfloat16(acc);
    g_Wch[r * CC + c] = hi;
    g_Wcl[r * CC + c] = __float2bfloat16(acc - __bfloat162float(hi));
    if (r == 0) {
        float bacc = q_b[c];
        for (int ch = 0; ch < YC; ch++) bacc += q_w[c * YC + ch] * head_b[ch & 63];
        g_zb[c] = bacc;
    }
}

// ---------------- 0b. split q_w to bf16 hi/lo --------------------------------
__global__ void convert_qw(const float* __restrict__ q_w) {
    int i = blockIdx.x * 512 + threadIdx.x;
    if (i < CC * YC) {
        float v = q_w[i];
        __nv_bfloat16 hi = __float2bfloat16(v);
        g_qwh[i] = hi;
        g_qwl[i] = __float2bfloat16(v - __bfloat162float(hi));
    }
}

// ---------------- 0c. transpose + split x: xt[P][c] bf16 hi/lo --------------
__global__ void transpose_split_x(const float* __restrict__ x) {
    __shared__ float s[32][33];
    const int bx = blockIdx.x;   // hw tile
    const int by = blockIdx.y;   // c tile
    const int b  = blockIdx.z;
    const int tx = threadIdx.x, ty = threadIdx.y;
    const float* xb = x + ((size_t)b * CC + by * 32) * HWP + bx * 32;
    #pragma unroll
    for (int i = 0; i < 4; i++)
        s[ty + i * 8][tx] = xb[(size_t)(ty + i * 8) * HWP + tx];
    __syncthreads();
    #pragma unroll
    for (int i = 0; i < 4; i++) {
        int hw = bx * 32 + ty + i * 8;
        int c  = by * 32 + tx;
        float v = s[tx][ty + i * 8];
        size_t o = ((size_t)(b * HWP + hw)) * CC + c;
        __nv_bfloat16 hi = __float2bfloat16(v);
        g_xth[o] = hi;
        g_xtl[o] = __float2bfloat16(v - __bfloat162float(hi));
    }
}

// ---------------- 1+3. pipelined warp-MMA GEMM (split-bf16, 3 products) -----
// C[M,N] = A[M,KTOT] . B[N,KTOT]^T ; CTA tile 128x128, 8 warps of 64x32.
// 2-stage cp.async double buffering on K-chunks of 64.
template<int KTOT, bool ZOUT>
__global__ __launch_bounds__(256) void gemm_mma(
    const __nv_bfloat16* __restrict__ Ah_g, const __nv_bfloat16* __restrict__ Al_g,
    const __nv_bfloat16* __restrict__ Bh_g, const __nv_bfloat16* __restrict__ Bl_g,
    float* __restrict__ outp)
{
    extern __shared__ __align__(16) char sm[];
    const uint32_t smb = smem_u32(sm);
    const int tid  = threadIdx.x;
    const int lane = tid & 31, wid = tid >> 5;
    const int wm = wid >> 2, wn = wid & 3;
    const int mt = blockIdx.y;
    const int P0 = blockIdx.x << 7;
    constexpr int KC = KTOT / 64;

    const __nv_bfloat16* Ah = Ah_g + (size_t)(mt * 128) * KTOT;
    const __nv_bfloat16* Al = Al_g + (size_t)(mt * 128) * KTOT;
    const __nv_bfloat16* Bh = Bh_g + (size_t)P0 * KTOT;
    const __nv_bfloat16* Bl = Bl_g + (size_t)P0 * KTOT;

    // per-thread static load coords
    const int lrow = tid >> 3;            // +128 per i-step of 2... (4 steps of 32 rows)
    const int lc16 = tid & 7;

    float c[4][4][4];
    #pragma unroll
    for (int i = 0; i < 4; i++)
        #pragma unroll
        for (int j = 0; j < 4; j++)
            #pragma unroll
            for (int k = 0; k < 4; k++) c[i][j][k] = 0.f;

    // ---- stage loader (cp.async) ----
    auto load_stage = [&](int kc, int stage) {
        const uint32_t sb = smb + stage * STAGE_BYTES;
        const int kb = kc * 64;
        #pragma unroll
        for (int i = 0; i < 4; i++) {
            int row = lrow + i * 32;
            size_t   go = (size_t)row * KTOT + kb + lc16 * 8;
            uint32_t so = row * SM_STRIDE + lc16 * 16;
            cp16(sb + OFF_AH + so, Ah + go);
            cp16(sb + OFF_AL + so, Al + go);
            cp16(sb + OFF_BH + so, Bh + go);
            cp16(sb + OFF_BL + so, Bl + go);
        }
        asm volatile("cp.async.commit_group;" ::: "memory");
    };

    load_stage(0, 0);

    for (int kc = 0; kc < KC; kc++) {
        if (kc + 1 < KC) {
            load_stage(kc + 1, (kc + 1) & 1);
            asm volatile("cp.async.wait_group 1;" ::: "memory");
        } else {
            asm volatile("cp.async.wait_group 0;" ::: "memory");
        }
        __syncthreads();
        const uint32_t sb = smb + (kc & 1) * STAGE_BYTES;
        #pragma unroll
        for (int ks = 0; ks < 4; ks++) {
            const int k0 = ks * 16;
            uint32_t bhf[4][2], blf[4][2];
            #pragma unroll
            for (int j = 0; j < 4; j++) {
                uint32_t brow = wn * 32 + j * 8 + (lane & 7);
                uint32_t bcol = k0 + ((lane >> 3) & 1) * 8;
                uint32_t a = sb + OFF_BH + brow * SM_STRIDE + bcol * 2;
                ldsm2(bhf[j], a);
                ldsm2(blf[j], a + (OFF_BL - OFF_BH));
            }
            #pragma unroll
            for (int i = 0; i < 4; i++) {
                uint32_t ahf[4], alf[4];
                uint32_t arow = wm * 64 + i * 16 + (lane & 15);
                uint32_t acol = k0 + (lane >> 4) * 8;
                uint32_t a = sb + OFF_AH + arow * SM_STRIDE + acol * 2;
                ldsm4(ahf, a);
                ldsm4(alf, a + (OFF_AL - OFF_AH));
                #pragma unroll
                for (int j = 0; j < 4; j++) {
                    mma16816(c[i][j], ahf, bhf[j]);
                    mma16816(c[i][j], ahf, blf[j]);
                    mma16816(c[i][j], alf, bhf[j]);
                }
            }
        }
        __syncthreads();
    }

    // epilogue via SMEM (reuse tile buffers)
    float* Cs = (float*)sm;
    #pragma unroll
    for (int i = 0; i < 4; i++)
        #pragma unroll
        for (int j = 0; j < 4; j++) {
            int r0 = wm * 64 + i * 16 + (lane >> 2);
            int nc = wn * 32 + j * 8 + (lane & 3) * 2;
            if (ZOUT) {
                Cs[r0 * 132 + nc]           = c[i][j][0];
                Cs[r0 * 132 + nc + 1]       = c[i][j][1];
                Cs[(r0 + 8) * 132 + nc]     = c[i][j][2];
                Cs[(r0 + 8) * 132 + nc + 1] = c[i][j][3];
            } else {
                Cs[nc * 132 + r0]           = c[i][j][0];
                Cs[(nc + 1) * 132 + r0]     = c[i][j][1];
                Cs[nc * 132 + r0 + 8]       = c[i][j][2];
                Cs[(nc + 1) * 132 + r0 + 8] = c[i][j][3];
            }
        }
    __syncthreads();
    if (ZOUT) {
        const int b = P0 >> 12, hw0 = P0 & 4095;
        float* ob = outp + (size_t)b * CC * HWP + hw0;
        #pragma unroll
        for (int s = 0; s < 16; s++) {
            int m  = s * 8 + wid;
            int oc = mt * 128 + m;
            float bias = g_zb[oc];
            float4 v = *(float4*)&Cs[m * 132 + lane * 4];
            v.x += bias; v.y += bias; v.z += bias; v.w += bias;
            *(float4*)(ob + (size_t)oc * HWP + lane * 4) = v;
        }
    } else {
        #pragma unroll
        for (int s = 0; s < 16; s++) {
            int p = s * 8 + wid;
            float4 v = *(float4*)&Cs[p * 132 + lane * 4];
            *(float4*)(g_G + (size_t)(P0 + p) * RGP + mt * 128 + lane * 4) = v;
        }
    }
}

// ---------------- 2. strip-mined window softmax + apply ---------------------
// 8 pixels per CTA along w. Strip of 3 rows x 10 cols of G in SMEM, shared.
__global__ __launch_bounds__(256) void attn_kernel() {
    __shared__ __align__(16) float as[3][10][64];
    __shared__ __align__(16) float us[3][10][256];
    __shared__ __align__(16) float A_s[2][64][12];   // stride 12 -> 16B-aligned rows
    const int tid = threadIdx.x;
    const int sub = tid >> 7;
    const int t   = tid & 127;
    const int P0  = blockIdx.x * 8;
    const int b   = P0 >> 12;
    const int hw0 = P0 & 4095;
    const int h = hw0 >> 6, w0 = hw0 & 63;

    // load strip: 30 positions x 80 float4
    for (int idx = tid; idx < 2400; idx += 256) {
        int pos = idx / 80;
        int r4  = idx - pos * 80;
        int rr = pos / 10, cl = pos - rr * 10;
        int hh = h + rr - 1;
        int ww = w0 + cl - 1;
        float4 v = make_float4(0.f, 0.f, 0.f, 0.f);
        if ((unsigned)hh < 64u && (unsigned)ww < 64u)
            v = ((const float4*)(g_G + (size_t)((b << 12) + (hh << 6) + ww) * RGP))[r4];
        int r = r4 << 2;
        if (r < 64) {
            as[rr][cl][r] = v.x; as[rr][cl][r + 1] = v.y;
            as[rr][cl][r + 2] = v.z; as[rr][cl][r + 3] = v.w;
        } else {
            int u0 = r - 64;
            us[rr][cl][u0] = v.x; us[rr][cl][u0 + 1] = v.y;
            us[rr][cl][u0 + 2] = v.z; us[rr][cl][u0 + 3] = v.w;
        }
    }
    __syncthreads();

    const int o  = t & 63;
    const int qb = t >> 6;

    for (int pp = 0; pp < 4; pp++) {
        const int px = pp * 2 + sub;
        // softmax over window for each (n,q) pair
        if (t < 64) {
            float vals[9];
            float m = -1e30f;
            #pragma unroll
            for (int r = 0; r < 3; r++)
                #pragma unroll
                for (int j = 0; j < 3; j++) {
                    float vv = as[r][px + j][t];
                    vals[r * 3 + j] = vv;
                    m = fmaxf(m, vv);
                }
            float e[9], s = 0.f;
            #pragma unroll
            for (int l = 0; l < 9; l++) { e[l] = __expf(vals[l] - m); s += e[l]; }
            float inv = 1.f / s;
            #pragma unroll
            for (int l = 0; l < 9; l++) A_s[sub][t][l] = e[l] * inv;
        }
        __syncthreads();

        // gather u for this pixel's window (registers)
        float ur[4][9];
        #pragma unroll
        for (int n = 0; n < 4; n++)
            #pragma unroll
            for (int r = 0; r < 3; r++)
                #pragma unroll
                for (int j = 0; j < 3; j++)
                    ur[n][r * 3 + j] = us[r][px + j][n * 64 + o];

        const size_t base = (size_t)(P0 + px) * YC;
        #pragma unroll
        for (int ii = 0; ii < 8; ii++) {
            int q = qb + (ii << 1);
            float acc = 0.f;
            #pragma unroll
            for (int n = 0; n < 4; n++) {
                const float* Ar = A_s[sub][n * 16 + q];
                float4 a0 = *(const float4*)Ar;
                float4 a1 = *(const float4*)(Ar + 4);
                float  a8 = Ar[8];
                acc += a0.x * ur[n][0] + a0.y * ur[n][1] + a0.z * ur[n][2] + a0.w * ur[n][3]
                     + a1.x * ur[n][4] + a1.y * ur[n][5] + a1.z * ur[n][6] + a1.w * ur[n][7]
                     + a8 * ur[n][8];
            }
            __nv_bfloat16 hi = __float2bfloat16(acc);
            g_Yh[base + (q << 6) + o] = hi;
            g_Yl[base + (q << 6) + o] = __float2bfloat16(acc - __bfloat162float(hi));
        }
        __syncthreads();
    }
}

// ---------------- launcher ---------------------------------------------------
extern "C" void kernel_launch(void* const* d_in, const int* in_sizes, int n_in,
                              void* d_out, int out_size) {
    const float* x      = (const float*)d_in[0];
    const float* kv_w   = (const float*)d_in[1];
    const float* dot_w  = (const float*)d_in[2];
    const float* head_w = (const float*)d_in[3];
    const float* head_b = (const float*)d_in[4];
    const float* q_w    = (const float*)d_in[5];
    const float* q_b    = (const float*)d_in[6];
    float* out = (float*)d_out;

    cudaFuncSetAttribute(gemm_mma<256,  false>, cudaFuncAttributeMaxDynamicSharedMemorySize, SMEM_BYTES);
    cudaFuncSetAttribute(gemm_mma<1024, true >, cudaFuncAttributeMaxDynamicSharedMemorySize, SMEM_BYTES);

    precompute_kernel<<<RGP, CC>>>(kv_w, dot_w, head_w, head_b, q_w, q_b);
    convert_qw<<<(CC * YC + 511) / 512, 512>>>(q_w);
    transpose_split_x<<<dim3(HWP / 32, CC / 32, 4), dim3(32, 8)>>>(x);

    __nv_bfloat16 *wch, *wcl, *xth, *xtl, *qwh, *qwl, *yh, *yl;
    cudaGetSymbolAddress((void**)&wch, g_Wch);
    cudaGetSymbolAddress((void**)&wcl, g_Wcl);
    cudaGetSymbolAddress((void**)&xth, g_xth);
    cudaGetSymbolAddress((void**)&xtl, g_xtl);
    cudaGetSymbolAddress((void**)&qwh, g_qwh);
    cudaGetSymbolAddress((void**)&qwl, g_qwl);
    cudaGetSymbolAddress((void**)&yh, g_Yh);
    cudaGetSymbolAddress((void**)&yl, g_Yl);

    gemm_mma<256, false><<<dim3(NP / 128, 3), 256, SMEM_BYTES>>>(wch, wcl, xth, xtl, nullptr);
    attn_kernel<<<NP / 8, 256>>>();
    gemm_mma<1024, true><<<dim3(NP / 128, 2), 256, SMEM_BYTES>>>(qwh, qwl, yh, yl, out);
}

// round 5
// speedup vs baseline: 2.4908x; 1.5731x over previous
#include <cuda_runtime.h>
#include <cuda_bf16.h>
#include <stdint.h>

#define CC   256
#define HWP  4096
#define NP   16384
#define RGP  384          // padded combined rows (320 used: 64 attn + 256 u)
#define YC   1024

// ---------------- static device scratch ------------------------------------
__device__ __align__(16) __nv_bfloat16 g_Wch[RGP * CC];
__device__ __align__(16) __nv_bfloat16 g_Wcl[RGP * CC];
__device__ float g_zb[CC];
__device__ __align__(16) __nv_bfloat16 g_qwh[CC * YC];
__device__ __align__(16) __nv_bfloat16 g_qwl[CC * YC];
__device__ __align__(16) __nv_bfloat16 g_xth[(size_t)NP * CC];
__device__ __align__(16) __nv_bfloat16 g_xtl[(size_t)NP * CC];
__device__ __align__(16) float g_G[(size_t)NP * RGP];
__device__ __align__(16) __nv_bfloat16 g_Yh[(size_t)NP * YC];
__device__ __align__(16) __nv_bfloat16 g_Yl[(size_t)NP * YC];

// ---------------- warp-MMA helpers (target-neutral PTX, sm_80+) -------------
__device__ __forceinline__ uint32_t smem_u32(const void* p) {
    uint32_t a;
    asm("{ .reg .u64 t; cvta.to.shared.u64 t, %1; cvt.u32.u64 %0, t; }" : "=r"(a) : "l"(p));
    return a;
}
__device__ __forceinline__ void ldsm4(uint32_t* r, uint32_t a) {
    asm volatile("ldmatrix.sync.aligned.m8n8.x4.shared.b16 {%0,%1,%2,%3}, [%4];"
        : "=r"(r[0]), "=r"(r[1]), "=r"(r[2]), "=r"(r[3]) : "r"(a));
}
__device__ __forceinline__ void ldsm2(uint32_t* r, uint32_t a) {
    asm volatile("ldmatrix.sync.aligned.m8n8.x2.shared.b16 {%0,%1}, [%2];"
        : "=r"(r[0]), "=r"(r[1]) : "r"(a));
}
__device__ __forceinline__ void mma16816(float* c, const uint32_t* a, const uint32_t* b) {
    asm volatile(
        "mma.sync.aligned.m16n8k16.row.col.f32.bf16.bf16.f32 "
        "{%0,%1,%2,%3}, {%4,%5,%6,%7}, {%8,%9}, {%0,%1,%2,%3};"
        : "+f"(c[0]), "+f"(c[1]), "+f"(c[2]), "+f"(c[3])
        : "r"(a[0]), "r"(a[1]), "r"(a[2]), "r"(a[3]), "r"(b[0]), "r"(b[1]));
}
__device__ __forceinline__ void cp16(uint32_t s, const void* g) {
    asm volatile("cp.async.cg.shared.global [%0], [%1], 16;" :: "r"(s), "l"(g) : "memory");
}

// smem per stage: A 128x64h (hi,lo) + B 64x64h (hi,lo), padded stride 144B
#define SM_STRIDE 144
#define OFF_AH 0
#define OFF_AL 18432
#define OFF_BH 36864
#define OFF_BL 46080
#define STAGE_BYTES 55296
#define SMEM_BYTES (2 * STAGE_BYTES)   // 110592 -> 2 CTAs/SM

// ---------------- 0a. fold weights + split to bf16 hi/lo --------------------
__global__ void precompute_kernel(const float* __restrict__ kv_w,
                                  const float* __restrict__ dot_w,
                                  const float* __restrict__ head_w) {
    int r = blockIdx.x;     // 0..383
    int c = threadIdx.x;    // 0..255
    float acc = 0.f;
    if (r < 64) {
        int n = r >> 4;
        const float* dw = dot_w + r * 64;
        const float* kw = kv_w + (n * 64) * CC + c;
        #pragma unroll 8
        for (int d = 0; d < 64; d++) acc += dw[d] * kw[d * CC];
    } else if (r < 320) {
        int t = r - 64;
        int n = t >> 6, o = t & 63;
        const float* hw_ = head_w + o * CC + n * 64;
        const float* kw  = kv_w + (256 + n * 64) * CC + c;
        #pragma unroll 8
        for (int d = 0; d < 64; d++) acc += hw_[d] * kw[d * CC];
    }
    __nv_bfloat16 hi = __float2bfloat16(acc);
    g_Wch[r * CC + c] = hi;
    g_Wcl[r * CC + c] = __float2bfloat16(acc - __bfloat162float(hi));
}

// ---------------- 0b. combined bias (parallel reduction) --------------------
__global__ void zb_kernel(const float* __restrict__ q_w,
                          const float* __restrict__ head_b,
                          const float* __restrict__ q_b) {
    __shared__ float red[256];
    const int c = blockIdx.x, t = threadIdx.x;
    float acc = 0.f;
    for (int ch = t; ch < YC; ch += 256) acc += q_w[c * YC + ch] * head_b[ch & 63];
    red[t] = acc;
    __syncthreads();
    for (int s = 128; s > 0; s >>= 1) {
        if (t < s) red[t] += red[t + s];
        __syncthreads();
    }
    if (t == 0) g_zb[c] = red[0] + q_b[c];
}

// ---------------- 0c. split q_w to bf16 hi/lo --------------------------------
__global__ void convert_qw(const float* __restrict__ q_w) {
    int i = blockIdx.x * 512 + threadIdx.x;
    if (i < CC * YC) {
        float v = q_w[i];
        __nv_bfloat16 hi = __float2bfloat16(v);
        g_qwh[i] = hi;
        g_qwl[i] = __float2bfloat16(v - __bfloat162float(hi));
    }
}

// ---------------- 0d. transpose + split x: xt[P][c] bf16 hi/lo --------------
__global__ void transpose_split_x(const float* __restrict__ x) {
    __shared__ float s[32][33];
    const int bx = blockIdx.x;   // hw tile
    const int by = blockIdx.y;   // c tile
    const int b  = blockIdx.z;
    const int tx = threadIdx.x, ty = threadIdx.y;
    const float* xb = x + ((size_t)b * CC + by * 32) * HWP + bx * 32;
    #pragma unroll
    for (int i = 0; i < 4; i++)
        s[ty + i * 8][tx] = xb[(size_t)(ty + i * 8) * HWP + tx];
    __syncthreads();
    #pragma unroll
    for (int i = 0; i < 4; i++) {
        int hw = bx * 32 + ty + i * 8;
        int c  = by * 32 + tx;
        float v = s[tx][ty + i * 8];
        size_t o = ((size_t)(b * HWP + hw)) * CC + c;
        __nv_bfloat16 hi = __float2bfloat16(v);
        g_xth[o] = hi;
        g_xtl[o] = __float2bfloat16(v - __bfloat162float(hi));
    }
}

// ---------------- 1+3. pipelined warp-MMA GEMM (split-bf16, 3 products) -----
// C[M,N] = A[M,KTOT].B[N,KTOT]^T ; CTA tile 128x64, 8 warps (4M x 2N) of 32x32.
// 2-stage cp.async double buffering on K-chunks of 64, ONE sync per chunk.
template<int KTOT, bool ZOUT>
__global__ __launch_bounds__(256) void gemm_mma(
    const __nv_bfloat16* __restrict__ Ah_g, const __nv_bfloat16* __restrict__ Al_g,
    const __nv_bfloat16* __restrict__ Bh_g, const __nv_bfloat16* __restrict__ Bl_g,
    float* __restrict__ outp)
{
    extern __shared__ __align__(16) char sm[];
    const uint32_t smb = smem_u32(sm);
    const int tid  = threadIdx.x;
    const int lane = tid & 31, wid = tid >> 5;
    const int wm = wid >> 1, wn = wid & 1;
    const int mt = blockIdx.y;
    const int P0 = blockIdx.x << 6;
    constexpr int KC = KTOT / 64;

    const __nv_bfloat16* Ah = Ah_g + (size_t)(mt * 128) * KTOT;
    const __nv_bfloat16* Al = Al_g + (size_t)(mt * 128) * KTOT;
    const __nv_bfloat16* Bh = Bh_g + (size_t)P0 * KTOT;
    const __nv_bfloat16* Bl = Bl_g + (size_t)P0 * KTOT;

    float c[2][4][4];
    #pragma unroll
    for (int i = 0; i < 2; i++)
        #pragma unroll
        for (int j = 0; j < 4; j++)
            #pragma unroll
            for (int k = 0; k < 4; k++) c[i][j][k] = 0.f;

    const int lrow = tid >> 3;    // 0..31 base rows
    const int lc16 = tid & 7;

    auto load_stage = [&](int kc, int stage) {
        const uint32_t sb = smb + stage * STAGE_BYTES;
        const int kb = kc * 64;
        #pragma unroll
        for (int i = 0; i < 4; i++) {
            int row = lrow + i * 32;
            size_t   go = (size_t)row * KTOT + kb + lc16 * 8;
            uint32_t so = row * SM_STRIDE + lc16 * 16;
            cp16(sb + OFF_AH + so, Ah + go);
            cp16(sb + OFF_AL + so, Al + go);
            if (i < 2) {
                cp16(sb + OFF_BH + so, Bh + go);
                cp16(sb + OFF_BL + so, Bl + go);
            }
        }
        asm volatile("cp.async.commit_group;" ::: "memory");
    };

    load_stage(0, 0);

    for (int kc = 0; kc < KC; kc++) {
        asm volatile("cp.async.wait_group 0;" ::: "memory");
        __syncthreads();
        if (kc + 1 < KC) load_stage(kc + 1, (kc + 1) & 1);
        const uint32_t sb = smb + (kc & 1) * STAGE_BYTES;
        #pragma unroll
        for (int ks = 0; ks < 4; ks++) {
            const int k0 = ks * 16;
            uint32_t bhf[4][2], blf[4][2];
            #pragma unroll
            for (int j = 0; j < 4; j++) {
                uint32_t brow = wn * 32 + j * 8 + (lane & 7);
                uint32_t bcol = k0 + ((lane >> 3) & 1) * 8;
                uint32_t a = sb + OFF_BH + brow * SM_STRIDE + bcol * 2;
                ldsm2(bhf[j], a);
                ldsm2(blf[j], a + (OFF_BL - OFF_BH));
            }
            #pragma unroll
            for (int i = 0; i < 2; i++) {
                uint32_t ahf[4], alf[4];
                uint32_t arow = wm * 32 + i * 16 + (lane & 15);
                uint32_t acol = k0 + (lane >> 4) * 8;
                uint32_t a = sb + OFF_AH + arow * SM_STRIDE + acol * 2;
                ldsm4(ahf, a);
                ldsm4(alf, a + (OFF_AL - OFF_AH));
                #pragma unroll
                for (int j = 0; j < 4; j++) {
                    mma16816(c[i][j], ahf, bhf[j]);
                    mma16816(c[i][j], ahf, blf[j]);
                    mma16816(c[i][j], alf, bhf[j]);
                }
            }
        }
        __syncthreads();   // retire stage before next iteration's load overwrite
    }

    // epilogue via SMEM (reuse tile buffers)
    float* Cs = (float*)sm;
    #pragma unroll
    for (int i = 0; i < 2; i++)
        #pragma unroll
        for (int j = 0; j < 4; j++) {
            int r0 = wm * 32 + i * 16 + (lane >> 2);
            int nc = wn * 32 + j * 8 + (lane & 3) * 2;
            if (ZOUT) {
                Cs[r0 * 68 + nc]           = c[i][j][0];
                Cs[r0 * 68 + nc + 1]       = c[i][j][1];
                Cs[(r0 + 8) * 68 + nc]     = c[i][j][2];
                Cs[(r0 + 8) * 68 + nc + 1] = c[i][j][3];
            } else {
                Cs[nc * 132 + r0]           = c[i][j][0];
                Cs[(nc + 1) * 132 + r0]     = c[i][j][1];
                Cs[nc * 132 + r0 + 8]       = c[i][j][2];
                Cs[(nc + 1) * 132 + r0 + 8] = c[i][j][3];
            }
        }
    __syncthreads();
    if (ZOUT) {
        const int b = P0 >> 12, hw0 = P0 & 4095;
        float* ob = outp + (size_t)b * CC * HWP + hw0;
        const int col = (lane & 15) * 4;
        #pragma unroll
        for (int s = 0; s < 8; s++) {
            int m  = s * 16 + wid * 2 + (lane >> 4);
            int oc = mt * 128 + m;
            float bias = g_zb[oc];
            float4 v = *(float4*)&Cs[m * 68 + col];
            v.x += bias; v.y += bias; v.z += bias; v.w += bias;
            *(float4*)(ob + (size_t)oc * HWP + col) = v;
        }
    } else {
        #pragma unroll
        for (int s = 0; s < 8; s++) {
            int n = s * 8 + wid;   // pixel within tile
            float4 v = *(float4*)&Cs[n * 132 + lane * 4];
            *(float4*)(g_G + (size_t)(P0 + n) * RGP + mt * 128 + lane * 4) = v;
        }
    }
}

// ---------------- 2. strip-mined window softmax + apply ---------------------
// 8 pixels per CTA along w. Strip of 3 rows x 10 cols of G in SMEM, shared.
__global__ __launch_bounds__(256) void attn_kernel() {
    __shared__ __align__(16) float as[3][10][64];
    __shared__ __align__(16) float us[3][10][256];
    __shared__ __align__(16) float A_s[2][64][12];
    const int tid = threadIdx.x;
    const int sub = tid >> 7;
    const int t   = tid & 127;
    const int P0  = blockIdx.x * 8;
    const int b   = P0 >> 12;
    const int hw0 = P0 & 4095;
    const int h = hw0 >> 6, w0 = hw0 & 63;

    for (int idx = tid; idx < 2400; idx += 256) {
        int pos = idx / 80;
        int r4  = idx - pos * 80;
        int rr = pos / 10, cl = pos - rr * 10;
        int hh = h + rr - 1;
        int ww = w0 + cl - 1;
        float4 v = make_float4(0.f, 0.f, 0.f, 0.f);
        if ((unsigned)hh < 64u && (unsigned)ww < 64u)
            v = ((const float4*)(g_G + (size_t)((b << 12) + (hh << 6) + ww) * RGP))[r4];
        int r = r4 << 2;
        if (r < 64) {
            as[rr][cl][r] = v.x; as[rr][cl][r + 1] = v.y;
            as[rr][cl][r + 2] = v.z; as[rr][cl][r + 3] = v.w;
        } else {
            int u0 = r - 64;
            us[rr][cl][u0] = v.x; us[rr][cl][u0 + 1] = v.y;
            us[rr][cl][u0 + 2] = v.z; us[rr][cl][u0 + 3] = v.w;
        }
    }
    __syncthreads();

    const int o  = t & 63;
    const int qb = t >> 6;

    for (int pp = 0; pp < 4; pp++) {
        const int px = pp * 2 + sub;
        if (t < 64) {
            float vals[9];
            float m = -1e30f;
            #pragma unroll
            for (int r = 0; r < 3; r++)
                #pragma unroll
                for (int j = 0; j < 3; j++) {
                    float vv = as[r][px + j][t];
                    vals[r * 3 + j] = vv;
                    m = fmaxf(m, vv);
                }
            float e[9], s = 0.f;
            #pragma unroll
            for (int l = 0; l < 9; l++) { e[l] = __expf(vals[l] - m); s += e[l]; }
            float inv = 1.f / s;
            #pragma unroll
            for (int l = 0; l < 9; l++) A_s[sub][t][l] = e[l] * inv;
        }
        __syncthreads();

        float ur[4][9];
        #pragma unroll
        for (int n = 0; n < 4; n++)
            #pragma unroll
            for (int r = 0; r < 3; r++)
                #pragma unroll
                for (int j = 0; j < 3; j++)
                    ur[n][r * 3 + j] = us[r][px + j][n * 64 + o];

        const size_t base = (size_t)(P0 + px) * YC;
        #pragma unroll
        for (int ii = 0; ii < 8; ii++) {
            int q = qb + (ii << 1);
            float acc = 0.f;
            #pragma unroll
            for (int n = 0; n < 4; n++) {
                const float* Ar = A_s[sub][n * 16 + q];
                float4 a0 = *(const float4*)Ar;
                float4 a1 = *(const float4*)(Ar + 4);
                float  a8 = Ar[8];
                acc += a0.x * ur[n][0] + a0.y * ur[n][1] + a0.z * ur[n][2] + a0.w * ur[n][3]
                     + a1.x * ur[n][4] + a1.y * ur[n][5] + a1.z * ur[n][6] + a1.w * ur[n][7]
                     + a8 * ur[n][8];
            }
            __nv_bfloat16 hi = __float2bfloat16(acc);
            g_Yh[base + (q << 6) + o] = hi;
            g_Yl[base + (q << 6) + o] = __float2bfloat16(acc - __bfloat162float(hi));
        }
        __syncthreads();
    }
}

// ---------------- launcher ---------------------------------------------------
extern "C" void kernel_launch(void* const* d_in, const int* in_sizes, int n_in,
                              void* d_out, int out_size) {
    const float* x      = (const float*)d_in[0];
    const float* kv_w   = (const float*)d_in[1];
    const float* dot_w  = (const float*)d_in[2];
    const float* head_w = (const float*)d_in[3];
    const float* head_b = (const float*)d_in[4];
    const float* q_w    = (const float*)d_in[5];
    const float* q_b    = (const float*)d_in[6];
    float* out = (float*)d_out;

    cudaFuncSetAttribute(gemm_mma<256,  false>, cudaFuncAttributeMaxDynamicSharedMemorySize, SMEM_BYTES);
    cudaFuncSetAttribute(gemm_mma<1024, true >, cudaFuncAttributeMaxDynamicSharedMemorySize, SMEM_BYTES);

    precompute_kernel<<<RGP, CC>>>(kv_w, dot_w, head_w);
    zb_kernel<<<CC, 256>>>(q_w, head_b, q_b);
    convert_qw<<<(CC * YC + 511) / 512, 512>>>(q_w);
    transpose_split_x<<<dim3(HWP / 32, CC / 32, 4), dim3(32, 8)>>>(x);

    __nv_bfloat16 *wch, *wcl, *xth, *xtl, *qwh, *qwl, *yh, *yl;
    cudaGetSymbolAddress((void**)&wch, g_Wch);
    cudaGetSymbolAddress((void**)&wcl, g_Wcl);
    cudaGetSymbolAddress((void**)&xth, g_xth);
    cudaGetSymbolAddress((void**)&xtl, g_xtl);
    cudaGetSymbolAddress((void**)&qwh, g_qwh);
    cudaGetSymbolAddress((void**)&qwl, g_qwl);
    cudaGetSymbolAddress((void**)&yh, g_Yh);
    cudaGetSymbolAddress((void**)&yl, g_Yl);

    gemm_mma<256, false><<<dim3(NP / 64, 3), 256, SMEM_BYTES>>>(wch, wcl, xth, xtl, nullptr);
    attn_kernel<<<NP / 8, 256>>>();
    gemm_mma<1024, true><<<dim3(NP / 64, 2), 256, SMEM_BYTES>>>(qwh, qwl, yh, yl, out);
}

// round 6
// speedup vs baseline: 2.8289x; 1.1357x over previous
#include <cuda_runtime.h>
#include <cuda_bf16.h>
#include <cuda_fp16.h>
#include <stdint.h>

#define CC   256
#define HWP  4096
#define NP   16384
#define RGP  384          // padded combined rows (320 used: 64 attn + 256 u)
#define YC   1024

// ---------------- static device scratch ------------------------------------
__device__ __align__(16) __nv_bfloat16 g_Wch[RGP * CC];
__device__ __align__(16) __nv_bfloat16 g_Wcl[RGP * CC];
__device__ float g_zb[CC];
__device__ __align__(16) __half g_qwh[CC * YC];   // q_w * 64, fp16 hi
__device__ __align__(16) __half g_qwl[CC * YC];   // q_w * 64, fp16 lo
__device__ __align__(16) __nv_bfloat16 g_xth[(size_t)NP * CC];
__device__ __align__(16) __nv_bfloat16 g_xtl[(size_t)NP * CC];
__device__ __align__(16) float g_G[(size_t)NP * RGP];
__device__ __align__(16) __half g_Yf[(size_t)NP * YC];   // Y, plain fp16

// ---------------- warp-MMA helpers (target-neutral PTX, sm_80+) -------------
__device__ __forceinline__ uint32_t smem_u32(const void* p) {
    uint32_t a;
    asm("{ .reg .u64 t; cvta.to.shared.u64 t, %1; cvt.u32.u64 %0, t; }" : "=r"(a) : "l"(p));
    return a;
}
__device__ __forceinline__ void ldsm4(uint32_t* r, uint32_t a) {
    asm volatile("ldmatrix.sync.aligned.m8n8.x4.shared.b16 {%0,%1,%2,%3}, [%4];"
        : "=r"(r[0]), "=r"(r[1]), "=r"(r[2]), "=r"(r[3]) : "r"(a));
}
__device__ __forceinline__ void ldsm2(uint32_t* r, uint32_t a) {
    asm volatile("ldmatrix.sync.aligned.m8n8.x2.shared.b16 {%0,%1}, [%2];"
        : "=r"(r[0]), "=r"(r[1]) : "r"(a));
}
__device__ __forceinline__ void mma16816(float* c, const uint32_t* a, const uint32_t* b) {
    asm volatile(
        "mma.sync.aligned.m16n8k16.row.col.f32.bf16.bf16.f32 "
        "{%0,%1,%2,%3}, {%4,%5,%6,%7}, {%8,%9}, {%0,%1,%2,%3};"
        : "+f"(c[0]), "+f"(c[1]), "+f"(c[2]), "+f"(c[3])
        : "r"(a[0]), "r"(a[1]), "r"(a[2]), "r"(a[3]), "r"(b[0]), "r"(b[1]));
}
__device__ __forceinline__ void mma16816h(float* c, const uint32_t* a, const uint32_t* b) {
    asm volatile(
        "mma.sync.aligned.m16n8k16.row.col.f32.f16.f16.f32 "
        "{%0,%1,%2,%3}, {%4,%5,%6,%7}, {%8,%9}, {%0,%1,%2,%3};"
        : "+f"(c[0]), "+f"(c[1]), "+f"(c[2]), "+f"(c[3])
        : "r"(a[0]), "r"(a[1]), "r"(a[2]), "r"(a[3]), "r"(b[0]), "r"(b[1]));
}
__device__ __forceinline__ void cp16(uint32_t s, const void* g) {
    asm volatile("cp.async.cg.shared.global [%0], [%1], 16;" :: "r"(s), "l"(g) : "memory");
}

#define SM_STRIDE 144

// gemm_G stage: A(hi,lo) 128x64h + B(hi,lo) 64x64h
#define G_OFF_AH 0
#define G_OFF_AL 18432
#define G_OFF_BH 36864
#define G_OFF_BL 46080
#define G_STAGE  55296
#define G_SMEM   (2 * G_STAGE)     // 110592 -> 2 CTAs/SM

// gemm_Z stage: A(hi,lo) 128x64h + B 64x64h (single fp16)
#define Z_OFF_AH 0
#define Z_OFF_AL 18432
#define Z_OFF_B  36864
#define Z_STAGE  46080
#define Z_SMEM   (2 * Z_STAGE)     // 92160 -> 2 CTAs/SM

// ---------------- 0a. fold weights + split to bf16 hi/lo --------------------
__global__ void precompute_kernel(const float* __restrict__ kv_w,
                                  const float* __restrict__ dot_w,
                                  const float* __restrict__ head_w) {
    int r = blockIdx.x;     // 0..383
    int c = threadIdx.x;    // 0..255
    float acc = 0.f;
    if (r < 64) {
        int n = r >> 4;
        const float* dw = dot_w + r * 64;
        const float* kw = kv_w + (n * 64) * CC + c;
        #pragma unroll 8
        for (int d = 0; d < 64; d++) acc += dw[d] * kw[d * CC];
    } else if (r < 320) {
        int t = r - 64;
        int n = t >> 6, o = t & 63;
        const float* hw_ = head_w + o * CC + n * 64;
        const float* kw  = kv_w + (256 + n * 64) * CC + c;
        #pragma unroll 8
        for (int d = 0; d < 64; d++) acc += hw_[d] * kw[d * CC];
    }
    __nv_bfloat16 hi = __float2bfloat16(acc);
    g_Wch[r * CC + c] = hi;
    g_Wcl[r * CC + c] = __float2bfloat16(acc - __bfloat162float(hi));
}

// ---------------- 0b. combined bias (parallel reduction) --------------------
__global__ void zb_kernel(const float* __restrict__ q_w,
                          const float* __restrict__ head_b,
                          const float* __restrict__ q_b) {
    __shared__ float red[256];
    const int c = blockIdx.x, t = threadIdx.x;
    float acc = 0.f;
    for (int ch = t; ch < YC; ch += 256) acc += q_w[c * YC + ch] * head_b[ch & 63];
    red[t] = acc;
    __syncthreads();
    for (int s = 128; s > 0; s >>= 1) {
        if (t < s) red[t] += red[t + s];
        __syncthreads();
    }
    if (t == 0) g_zb[c] = red[0] + q_b[c];
}

// ---------------- 0c. split q_w*64 to fp16 hi/lo -----------------------------
__global__ void convert_qw(const float* __restrict__ q_w) {
    int i = blockIdx.x * 512 + threadIdx.x;
    if (i < CC * YC) {
        float v = q_w[i] * 64.f;
        __half hi = __float2half(v);
        g_qwh[i] = hi;
        g_qwl[i] = __float2half(v - __half2float(hi));
    }
}

// ---------------- 0d. transpose + split x: xt[P][c] bf16 hi/lo --------------
__global__ void transpose_split_x(const float* __restrict__ x) {
    __shared__ float s[32][33];
    const int bx = blockIdx.x;   // hw tile
    const int by = blockIdx.y;   // c tile
    const int b  = blockIdx.z;
    const int tx = threadIdx.x, ty = threadIdx.y;
    const float* xb = x + ((size_t)b * CC + by * 32) * HWP + bx * 32;
    #pragma unroll
    for (int i = 0; i < 4; i++)
        s[ty + i * 8][tx] = xb[(size_t)(ty + i * 8) * HWP + tx];
    __syncthreads();
    #pragma unroll
    for (int i = 0; i < 4; i++) {
        int hw = bx * 32 + ty + i * 8;
        int c  = by * 32 + tx;
        float v = s[tx][ty + i * 8];
        size_t o = ((size_t)(b * HWP + hw)) * CC + c;
        __nv_bfloat16 hi = __float2bfloat16(v);
        g_xth[o] = hi;
        g_xtl[o] = __float2bfloat16(v - __bfloat162float(hi));
    }
}

// ---------------- 1. gemm_G: bf16 split 3-product (unchanged engine) --------
// C[M=384,N=16384] tile 128x64, 8 warps (4M x 2N) of 32x32.
__global__ __launch_bounds__(256) void gemm_G(
    const __nv_bfloat16* __restrict__ Ah_g, const __nv_bfloat16* __restrict__ Al_g,
    const __nv_bfloat16* __restrict__ Bh_g, const __nv_bfloat16* __restrict__ Bl_g)
{
    extern __shared__ __align__(16) char sm[];
    const uint32_t smb = smem_u32(sm);
    const int tid  = threadIdx.x;
    const int lane = tid & 31, wid = tid >> 5;
    const int wm = wid >> 1, wn = wid & 1;
    const int mt = blockIdx.y;
    const int P0 = blockIdx.x << 6;
    constexpr int KTOT = 256;
    constexpr int KC = 4;

    const __nv_bfloat16* Ah = Ah_g + (size_t)(mt * 128) * KTOT;
    const __nv_bfloat16* Al = Al_g + (size_t)(mt * 128) * KTOT;
    const __nv_bfloat16* Bh = Bh_g + (size_t)P0 * KTOT;
    const __nv_bfloat16* Bl = Bl_g + (size_t)P0 * KTOT;

    float c[2][4][4];
    #pragma unroll
    for (int i = 0; i < 2; i++)
        #pragma unroll
        for (int j = 0; j < 4; j++)
            #pragma unroll
            for (int k = 0; k < 4; k++) c[i][j][k] = 0.f;

    const int lrow = tid >> 3;
    const int lc16 = tid & 7;

    auto load_stage = [&](int kc, int stage) {
        const uint32_t sb = smb + stage * G_STAGE;
        const int kb = kc * 64;
        #pragma unroll
        for (int i = 0; i < 4; i++) {
            int row = lrow + i * 32;
            size_t   go = (size_t)row * KTOT + kb + lc16 * 8;
            uint32_t so = row * SM_STRIDE + lc16 * 16;
            cp16(sb + G_OFF_AH + so, Ah + go);
            cp16(sb + G_OFF_AL + so, Al + go);
            if (i < 2) {
                cp16(sb + G_OFF_BH + so, Bh + go);
                cp16(sb + G_OFF_BL + so, Bl + go);
            }
        }
        asm volatile("cp.async.commit_group;" ::: "memory");
    };

    load_stage(0, 0);

    for (int kc = 0; kc < KC; kc++) {
        asm volatile("cp.async.wait_group 0;" ::: "memory");
        __syncthreads();
        if (kc + 1 < KC) load_stage(kc + 1, (kc + 1) & 1);
        const uint32_t sb = smb + (kc & 1) * G_STAGE;
        #pragma unroll
        for (int ks = 0; ks < 4; ks++) {
            const int k0 = ks * 16;
            uint32_t bhf[4][2], blf[4][2];
            #pragma unroll
            for (int j = 0; j < 4; j++) {
                uint32_t brow = wn * 32 + j * 8 + (lane & 7);
                uint32_t bcol = k0 + ((lane >> 3) & 1) * 8;
                uint32_t a = sb + G_OFF_BH + brow * SM_STRIDE + bcol * 2;
                ldsm2(bhf[j], a);
                ldsm2(blf[j], a + (G_OFF_BL - G_OFF_BH));
            }
            #pragma unroll
            for (int i = 0; i < 2; i++) {
                uint32_t ahf[4], alf[4];
                uint32_t arow = wm * 32 + i * 16 + (lane & 15);
                uint32_t acol = k0 + (lane >> 4) * 8;
                uint32_t a = sb + G_OFF_AH + arow * SM_STRIDE + acol * 2;
                ldsm4(ahf, a);
                ldsm4(alf, a + (G_OFF_AL - G_OFF_AH));
                #pragma unroll
                for (int j = 0; j < 4; j++) {
                    mma16816(c[i][j], ahf, bhf[j]);
                    mma16816(c[i][j], ahf, blf[j]);
                    mma16816(c[i][j], alf, bhf[j]);
                }
            }
        }
        __syncthreads();
    }

    // epilogue: transpose to pixel-major G
    float* Cs = (float*)sm;
    #pragma unroll
    for (int i = 0; i < 2; i++)
        #pragma unroll
        for (int j = 0; j < 4; j++) {
            int r0 = wm * 32 + i * 16 + (lane >> 2);
            int nc = wn * 32 + j * 8 + (lane & 3) * 2;
            Cs[nc * 132 + r0]           = c[i][j][0];
            Cs[(nc + 1) * 132 + r0]     = c[i][j][1];
            Cs[nc * 132 + r0 + 8]       = c[i][j][2];
            Cs[(nc + 1) * 132 + r0 + 8] = c[i][j][3];
        }
    __syncthreads();
    #pragma unroll
    for (int s = 0; s < 8; s++) {
        int n = s * 8 + wid;
        float4 v = *(float4*)&Cs[n * 132 + lane * 4];
        *(float4*)(g_G + (size_t)(P0 + n) * RGP + mt * 128 + lane * 4) = v;
    }
}

// ---------------- 3. gemm_Z: fp16 asymmetric split, 2-product ----------------
// z[oc][P] = (1/64) * sum_ch (64*qw)[oc][ch] * Yf[P][ch] + zb
__global__ __launch_bounds__(256) void gemm_Z(
    const __half* __restrict__ Ah_g, const __half* __restrict__ Al_g,
    const __half* __restrict__ B_g, float* __restrict__ outp)
{
    extern __shared__ __align__(16) char sm[];
    const uint32_t smb = smem_u32(sm);
    const int tid  = threadIdx.x;
    const int lane = tid & 31, wid = tid >> 5;
    const int wm = wid >> 1, wn = wid & 1;
    const int mt = blockIdx.y;
    const int P0 = blockIdx.x << 6;
    constexpr int KTOT = 1024;
    constexpr int KC = 16;

    const __half* Ah = Ah_g + (size_t)(mt * 128) * KTOT;
    const __half* Al = Al_g + (size_t)(mt * 128) * KTOT;
    const __half* Bg = B_g + (size_t)P0 * KTOT;

    float c[2][4][4];
    #pragma unroll
    for (int i = 0; i < 2; i++)
        #pragma unroll
        for (int j = 0; j < 4; j++)
            #pragma unroll
            for (int k = 0; k < 4; k++) c[i][j][k] = 0.f;

    const int lrow = tid >> 3;
    const int lc16 = tid & 7;

    auto load_stage = [&](int kc, int stage) {
        const uint32_t sb = smb + stage * Z_STAGE;
        const int kb = kc * 64;
        #pragma unroll
        for (int i = 0; i < 4; i++) {
            int row = lrow + i * 32;
            size_t   go = (size_t)row * KTOT + kb + lc16 * 8;
            uint32_t so = row * SM_STRIDE + lc16 * 16;
            cp16(sb + Z_OFF_AH + so, Ah + go);
            cp16(sb + Z_OFF_AL + so, Al + go);
            if (i < 2) cp16(sb + Z_OFF_B + so, Bg + go);
        }
        asm volatile("cp.async.commit_group;" ::: "memory");
    };

    load_stage(0, 0);

    for (int kc = 0; kc < KC; kc++) {
        asm volatile("cp.async.wait_group 0;" ::: "memory");
        __syncthreads();
        if (kc + 1 < KC) load_stage(kc + 1, (kc + 1) & 1);
        const uint32_t sb = smb + (kc & 1) * Z_STAGE;
        #pragma unroll
        for (int ks = 0; ks < 4; ks++) {
            const int k0 = ks * 16;
            uint32_t bf[4][2];
            #pragma unroll
            for (int j = 0; j < 4; j++) {
                uint32_t brow = wn * 32 + j * 8 + (lane & 7);
                uint32_t bcol = k0 + ((lane >> 3) & 1) * 8;
                ldsm2(bf[j], sb + Z_OFF_B + brow * SM_STRIDE + bcol * 2);
            }
            #pragma unroll
            for (int i = 0; i < 2; i++) {
                uint32_t ahf[4], alf[4];
                uint32_t arow = wm * 32 + i * 16 + (lane & 15);
                uint32_t acol = k0 + (lane >> 4) * 8;
                uint32_t a = sb + Z_OFF_AH + arow * SM_STRIDE + acol * 2;
                ldsm4(ahf, a);
                ldsm4(alf, a + (Z_OFF_AL - Z_OFF_AH));
                #pragma unroll
                for (int j = 0; j < 4; j++) {
                    mma16816h(c[i][j], ahf, bf[j]);
                    mma16816h(c[i][j], alf, bf[j]);
                }
            }
        }
        __syncthreads();
    }

    // epilogue: row-major through SMEM, scale 1/64 + bias, coalesced stores
    float* Cs = (float*)sm;
    #pragma unroll
    for (int i = 0; i < 2; i++)
        #pragma unroll
        for (int j = 0; j < 4; j++) {
            int r0 = wm * 32 + i * 16 + (lane >> 2);
            int nc = wn * 32 + j * 8 + (lane & 3) * 2;
            Cs[r0 * 68 + nc]           = c[i][j][0];
            Cs[r0 * 68 + nc + 1]       = c[i][j][1];
            Cs[(r0 + 8) * 68 + nc]     = c[i][j][2];
            Cs[(r0 + 8) * 68 + nc + 1] = c[i][j][3];
        }
    __syncthreads();
    const int b = P0 >> 12, hw0 = P0 & 4095;
    float* ob = outp + (size_t)b * CC * HWP + hw0;
    const int col = (lane & 15) * 4;
    const float inv64 = 1.f / 64.f;
    #pragma unroll
    for (int s = 0; s < 8; s++) {
        int m  = s * 16 + wid * 2 + (lane >> 4);
        int oc = mt * 128 + m;
        float bias = g_zb[oc];
        float4 v = *(float4*)&Cs[m * 68 + col];
        v.x = v.x * inv64 + bias; v.y = v.y * inv64 + bias;
        v.z = v.z * inv64 + bias; v.w = v.w * inv64 + bias;
        *(float4*)(ob + (size_t)oc * HWP + col) = v;
    }
}

// ---------------- 2. strip-mined window softmax + apply ---------------------
__global__ __launch_bounds__(256) void attn_kernel() {
    __shared__ __align__(16) float as[3][10][64];
    __shared__ __align__(16) float us[3][10][256];
    __shared__ __align__(16) float A_s[2][64][12];
    const int tid = threadIdx.x;
    const int sub = tid >> 7;
    const int t   = tid & 127;
    const int P0  = blockIdx.x * 8;
    const int b   = P0 >> 12;
    const int hw0 = P0 & 4095;
    const int h = hw0 >> 6, w0 = hw0 & 63;

    for (int idx = tid; idx < 2400; idx += 256) {
        int pos = idx / 80;
        int r4  = idx - pos * 80;
        int rr = pos / 10, cl = pos - rr * 10;
        int hh = h + rr - 1;
        int ww = w0 + cl - 1;
        float4 v = make_float4(0.f, 0.f, 0.f, 0.f);
        if ((unsigned)hh < 64u && (unsigned)ww < 64u)
            v = ((const float4*)(g_G + (size_t)((b << 12) + (hh << 6) + ww) * RGP))[r4];
        int r = r4 << 2;
        if (r < 64) {
            as[rr][cl][r] = v.x; as[rr][cl][r + 1] = v.y;
            as[rr][cl][r + 2] = v.z; as[rr][cl][r + 3] = v.w;
        } else {
            int u0 = r - 64;
            us[rr][cl][u0] = v.x; us[rr][cl][u0 + 1] = v.y;
            us[rr][cl][u0 + 2] = v.z; us[rr][cl][u0 + 3] = v.w;
        }
    }
    __syncthreads();

    const int o  = t & 63;
    const int qb = t >> 6;

    for (int pp = 0; pp < 4; pp++) {
        const int px = pp * 2 + sub;
        if (t < 64) {
            float vals[9];
            float m = -1e30f;
            #pragma unroll
            for (int r = 0; r < 3; r++)
                #pragma unroll
                for (int j = 0; j < 3; j++) {
                    float vv = as[r][px + j][t];
                    vals[r * 3 + j] = vv;
                    m = fmaxf(m, vv);
                }
            float e[9], s = 0.f;
            #pragma unroll
            for (int l = 0; l < 9; l++) { e[l] = __expf(vals[l] - m); s += e[l]; }
            float inv = 1.f / s;
            #pragma unroll
            for (int l = 0; l < 9; l++) A_s[sub][t][l] = e[l] * inv;
        }
        __syncthreads();

        float ur[4][9];
        #pragma unroll
        for (int n = 0; n < 4; n++)
            #pragma unroll
            for (int r = 0; r < 3; r++)
                #pragma unroll
                for (int j = 0; j < 3; j++)
                    ur[n][r * 3 + j] = us[r][px + j][n * 64 + o];

        const size_t base = (size_t)(P0 + px) * YC;
        #pragma unroll
        for (int ii = 0; ii < 8; ii++) {
            int q = qb + (ii << 1);
            float acc = 0.f;
            #pragma unroll
            for (int n = 0; n < 4; n++) {
                const float* Ar = A_s[sub][n * 16 + q];
                float4 a0 = *(const float4*)Ar;
                float4 a1 = *(const float4*)(Ar + 4);
                float  a8 = Ar[8];
                acc += a0.x * ur[n][0] + a0.y * ur[n][1] + a0.z * ur[n][2] + a0.w * ur[n][3]
                     + a1.x * ur[n][4] + a1.y * ur[n][5] + a1.z * ur[n][6] + a1.w * ur[n][7]
                     + a8 * ur[n][8];
            }
            g_Yf[base + (q << 6) + o] = __float2half(acc);
        }
        __syncthreads();
    }
}

// ---------------- launcher ---------------------------------------------------
extern "C" void kernel_launch(void* const* d_in, const int* in_sizes, int n_in,
                              void* d_out, int out_size) {
    const float* x      = (const float*)d_in[0];
    const float* kv_w   = (const float*)d_in[1];
    const float* dot_w  = (const float*)d_in[2];
    const float* head_w = (const float*)d_in[3];
    const float* head_b = (const float*)d_in[4];
    const float* q_w    = (const float*)d_in[5];
    const float* q_b    = (const float*)d_in[6];
    float* out = (float*)d_out;

    cudaFuncSetAttribute(gemm_G, cudaFuncAttributeMaxDynamicSharedMemorySize, G_SMEM);
    cudaFuncSetAttribute(gemm_Z, cudaFuncAttributeMaxDynamicSharedMemorySize, Z_SMEM);

    precompute_kernel<<<RGP, CC>>>(kv_w, dot_w, head_w);
    zb_kernel<<<CC, 256>>>(q_w, head_b, q_b);
    convert_qw<<<(CC * YC + 511) / 512, 512>>>(q_w);
    transpose_split_x<<<dim3(HWP / 32, CC / 32, 4), dim3(32, 8)>>>(x);

    __nv_bfloat16 *wch, *wcl, *xth, *xtl;
    __half *qwh, *qwl, *yf;
    cudaGetSymbolAddress((void**)&wch, g_Wch);
    cudaGetSymbolAddress((void**)&wcl, g_Wcl);
    cudaGetSymbolAddress((void**)&xth, g_xth);
    cudaGetSymbolAddress((void**)&xtl, g_xtl);
    cudaGetSymbolAddress((void**)&qwh, g_qwh);
    cudaGetSymbolAddress((void**)&qwl, g_qwl);
    cudaGetSymbolAddress((void**)&yf, g_Yf);

    gemm_G<<<dim3(NP / 64, 3), 256, G_SMEM>>>(wch, wcl, xth, xtl);
    attn_kernel<<<NP / 8, 256>>>();
    gemm_Z<<<dim3(NP / 64, 2), 256, Z_SMEM>>>(qwh, qwl, yf, out);
}

// round 7
// speedup vs baseline: 3.2042x; 1.1327x over previous
#include <cuda_runtime.h>
#include <cuda_bf16.h>
#include <cuda_fp16.h>
#include <stdint.h>

#define CC   256
#define HWP  4096
#define NP   16384
#define RGP  384          // padded combined rows (320 used: 64 attn + 256 u)
#define YC   1024

// ---------------- static device scratch ------------------------------------
__device__ __align__(16) __half g_Wch[RGP * CC];      // Wc*256 fp16 hi
__device__ __align__(16) __half g_Wcl[RGP * CC];      // Wc*256 fp16 lo
__device__ float g_zb[CC];
__device__ __align__(16) __half g_qwh[CC * YC];       // q_w*64 fp16 hi
__device__ __align__(16) __half g_qwl[CC * YC];       // q_w*64 fp16 lo
__device__ __align__(16) __half g_xt[(size_t)NP * CC];// x transposed, fp16
__device__ __align__(16) float g_G[(size_t)NP * RGP];
__device__ __align__(16) __half g_Yf[(size_t)NP * YC];// Y, fp16

// ---------------- warp-MMA helpers (target-neutral PTX, sm_80+) -------------
__device__ __forceinline__ uint32_t smem_u32(const void* p) {
    uint32_t a;
    asm("{ .reg .u64 t; cvta.to.shared.u64 t, %1; cvt.u32.u64 %0, t; }" : "=r"(a) : "l"(p));
    return a;
}
__device__ __forceinline__ void ldsm4(uint32_t* r, uint32_t a) {
    asm volatile("ldmatrix.sync.aligned.m8n8.x4.shared.b16 {%0,%1,%2,%3}, [%4];"
        : "=r"(r[0]), "=r"(r[1]), "=r"(r[2]), "=r"(r[3]) : "r"(a));
}
__device__ __forceinline__ void ldsm2(uint32_t* r, uint32_t a) {
    asm volatile("ldmatrix.sync.aligned.m8n8.x2.shared.b16 {%0,%1}, [%2];"
        : "=r"(r[0]), "=r"(r[1]) : "r"(a));
}
__device__ __forceinline__ void mma16816h(float* c, const uint32_t* a, const uint32_t* b) {
    asm volatile(
        "mma.sync.aligned.m16n8k16.row.col.f32.f16.f16.f32 "
        "{%0,%1,%2,%3}, {%4,%5,%6,%7}, {%8,%9}, {%0,%1,%2,%3};"
        : "+f"(c[0]), "+f"(c[1]), "+f"(c[2]), "+f"(c[3])
        : "r"(a[0]), "r"(a[1]), "r"(a[2]), "r"(a[3]), "r"(b[0]), "r"(b[1]));
}
__device__ __forceinline__ void cp16(uint32_t s, const void* g) {
    asm volatile("cp.async.cg.shared.global [%0], [%1], 16;" :: "r"(s), "l"(g) : "memory");
}

#define SM_STRIDE 144
// stage: A hi 128x64h, A lo 128x64h, B 128x64h (each 128 rows x 144B)
#define OFF_AH 0
#define OFF_AL 18432
#define OFF_B  36864
#define STAGE_BYTES 55296
#define SMEM_BYTES (2 * STAGE_BYTES)   // 110592 -> 2 CTAs/SM

// ---------------- 0a. fold weights + split to fp16 hi/lo (x256) -------------
// rows 0..63  : attn rows (n*16+q)
// rows 64..319: u rows, REMAPPED to 64 + o*4 + n  (for attn float4 gather)
__global__ void precompute_kernel(const float* __restrict__ kv_w,
                                  const float* __restrict__ dot_w,
                                  const float* __restrict__ head_w) {
    int r = blockIdx.x;     // 0..383
    int c = threadIdx.x;    // 0..255
    float acc = 0.f;
    if (r < 64) {
        int n = r >> 4;
        const float* dw = dot_w + r * 64;
        const float* kw = kv_w + (n * 64) * CC + c;
        #pragma unroll 8
        for (int d = 0; d < 64; d++) acc += dw[d] * kw[d * CC];
    } else if (r < 320) {
        int t = r - 64;
        int o = t >> 2, n = t & 3;
        const float* hw_ = head_w + o * CC + n * 64;
        const float* kw  = kv_w + (256 + n * 64) * CC + c;
        #pragma unroll 8
        for (int d = 0; d < 64; d++) acc += hw_[d] * kw[d * CC];
    }
    float v = acc * 256.f;
    __half hi = __float2half(v);
    g_Wch[r * CC + c] = hi;
    g_Wcl[r * CC + c] = __float2half(v - __half2float(hi));
}

// ---------------- 0b. combined bias (parallel reduction) --------------------
__global__ void zb_kernel(const float* __restrict__ q_w,
                          const float* __restrict__ head_b,
                          const float* __restrict__ q_b) {
    __shared__ float red[256];
    const int c = blockIdx.x, t = threadIdx.x;
    float acc = 0.f;
    for (int ch = t; ch < YC; ch += 256) acc += q_w[c * YC + ch] * head_b[ch & 63];
    red[t] = acc;
    __syncthreads();
    for (int s = 128; s > 0; s >>= 1) {
        if (t < s) red[t] += red[t + s];
        __syncthreads();
    }
    if (t == 0) g_zb[c] = red[0] + q_b[c];
}

// ---------------- 0c. split q_w*64 to fp16 hi/lo -----------------------------
__global__ void convert_qw(const float* __restrict__ q_w) {
    int i = blockIdx.x * 512 + threadIdx.x;
    if (i < CC * YC) {
        float v = q_w[i] * 64.f;
        __half hi = __float2half(v);
        g_qwh[i] = hi;
        g_qwl[i] = __float2half(v - __half2float(hi));
    }
}

// ---------------- 0d. transpose x -> xt[P][c] fp16 ---------------------------
__global__ void transpose_half_x(const float* __restrict__ x) {
    __shared__ float s[32][33];
    const int bx = blockIdx.x;   // hw tile
    const int by = blockIdx.y;   // c tile
    const int b  = blockIdx.z;
    const int tx = threadIdx.x, ty = threadIdx.y;
    const float* xb = x + ((size_t)b * CC + by * 32) * HWP + bx * 32;
    #pragma unroll
    for (int i = 0; i < 4; i++)
        s[ty + i * 8][tx] = xb[(size_t)(ty + i * 8) * HWP + tx];
    __syncthreads();
    #pragma unroll
    for (int i = 0; i < 4; i++) {
        int hw = bx * 32 + ty + i * 8;
        int c  = by * 32 + tx;
        g_xt[((size_t)(b * HWP + hw)) * CC + c] = __float2half(s[tx][ty + i * 8]);
    }
}

// ---------------- 1+3. pipelined fp16 asymmetric-split GEMM -----------------
// C[M,N] = A[M,KTOT].B[N,KTOT]^T ; CTA tile 128x128, 8 warps (2M x 4N) of 64x32.
// A split hi/lo (2 MMAs), B plain fp16. 2-stage cp.async, 1 sync per chunk.
// ZOUT: row-major out + 1/64 scale + bias.  !ZOUT: transposed g_G + 1/256 scale.
template<int KTOT, bool ZOUT>
__global__ __launch_bounds__(256) void gemm_mma(
    const __half* __restrict__ Ah_g, const __half* __restrict__ Al_g,
    const __half* __restrict__ B_g, float* __restrict__ outp)
{
    extern __shared__ __align__(16) char sm[];
    const uint32_t smb = smem_u32(sm);
    const int tid  = threadIdx.x;
    const int lane = tid & 31, wid = tid >> 5;
    const int wm = wid >> 2, wn = wid & 3;
    const int mt = blockIdx.y;
    const int P0 = blockIdx.x << 7;
    constexpr int KC = KTOT / 64;

    const __half* Ah = Ah_g + (size_t)(mt * 128) * KTOT;
    const __half* Al = Al_g + (size_t)(mt * 128) * KTOT;
    const __half* Bg = B_g + (size_t)P0 * KTOT;

    float c[4][4][4];
    #pragma unroll
    for (int i = 0; i < 4; i++)
        #pragma unroll
        for (int j = 0; j < 4; j++)
            #pragma unroll
            for (int k = 0; k < 4; k++) c[i][j][k] = 0.f;

    const int lrow = tid >> 3;    // 0..31
    const int lc16 = tid & 7;

    auto load_stage = [&](int kc, int stage) {
        const uint32_t sb = smb + stage * STAGE_BYTES;
        const int kb = kc * 64;
        #pragma unroll
        for (int i = 0; i < 4; i++) {
            int row = lrow + i * 32;
            size_t   go = (size_t)row * KTOT + kb + lc16 * 8;
            uint32_t so = row * SM_STRIDE + lc16 * 16;
            cp16(sb + OFF_AH + so, Ah + go);
            cp16(sb + OFF_AL + so, Al + go);
            cp16(sb + OFF_B  + so, Bg + go);
        }
        asm volatile("cp.async.commit_group;" ::: "memory");
    };

    load_stage(0, 0);

    for (int kc = 0; kc < KC; kc++) {
        asm volatile("cp.async.wait_group 0;" ::: "memory");
        __syncthreads();
        if (kc + 1 < KC) load_stage(kc + 1, (kc + 1) & 1);
        const uint32_t sb = smb + (kc & 1) * STAGE_BYTES;
        #pragma unroll
        for (int ks = 0; ks < 4; ks++) {
            const int k0 = ks * 16;
            uint32_t bf[4][2];
            #pragma unroll
            for (int j = 0; j < 4; j++) {
                uint32_t brow = wn * 32 + j * 8 + (lane & 7);
                uint32_t bcol = k0 + ((lane >> 3) & 1) * 8;
                ldsm2(bf[j], sb + OFF_B + brow * SM_STRIDE + bcol * 2);
            }
            #pragma unroll
            for (int i = 0; i < 4; i++) {
                uint32_t ahf[4], alf[4];
                uint32_t arow = wm * 64 + i * 16 + (lane & 15);
                uint32_t acol = k0 + (lane >> 4) * 8;
                uint32_t a = sb + OFF_AH + arow * SM_STRIDE + acol * 2;
                ldsm4(ahf, a);
                ldsm4(alf, a + (OFF_AL - OFF_AH));
                #pragma unroll
                for (int j = 0; j < 4; j++) {
                    mma16816h(c[i][j], ahf, bf[j]);
                    mma16816h(c[i][j], alf, bf[j]);
                }
            }
        }
        __syncthreads();
    }

    // epilogue via SMEM (Cs = 128x132 floats = 67.6KB, fits in the 110.6KB buffer)
    float* Cs = (float*)sm;
    const float scale = ZOUT ? (1.f / 64.f) : (1.f / 256.f);
    #pragma unroll
    for (int i = 0; i < 4; i++)
        #pragma unroll
        for (int j = 0; j < 4; j++) {
            int r0 = wm * 64 + i * 16 + (lane >> 2);
            int nc = wn * 32 + j * 8 + (lane & 3) * 2;
            float v0 = c[i][j][0] * scale, v1 = c[i][j][1] * scale;
            float v2 = c[i][j][2] * scale, v3 = c[i][j][3] * scale;
            if (ZOUT) {
                Cs[r0 * 132 + nc]           = v0;
                Cs[r0 * 132 + nc + 1]       = v1;
                Cs[(r0 + 8) * 132 + nc]     = v2;
                Cs[(r0 + 8) * 132 + nc + 1] = v3;
            } else {
                Cs[nc * 132 + r0]           = v0;
                Cs[(nc + 1) * 132 + r0]     = v1;
                Cs[nc * 132 + r0 + 8]       = v2;
                Cs[(nc + 1) * 132 + r0 + 8] = v3;
            }
        }
    __syncthreads();
    if (ZOUT) {
        const int b = P0 >> 12, hw0 = P0 & 4095;
        float* ob = outp + (size_t)b * CC * HWP + hw0;
        #pragma unroll
        for (int s = 0; s < 16; s++) {
            int m  = s * 8 + wid;
            int oc = mt * 128 + m;
            float bias = g_zb[oc];
            float4 v = *(float4*)&Cs[m * 132 + lane * 4];
            v.x += bias; v.y += bias; v.z += bias; v.w += bias;
            *(float4*)(ob + (size_t)oc * HWP + lane * 4) = v;
        }
    } else {
        #pragma unroll
        for (int s = 0; s < 16; s++) {
            int p = s * 8 + wid;
            float4 v = *(float4*)&Cs[p * 132 + lane * 4];
            *(float4*)(g_G + (size_t)(P0 + p) * RGP + mt * 128 + lane * 4) = v;
        }
    }
}

// ---------------- 2. strip-mined window softmax + apply ---------------------
// 8 pixels/CTA along w. G u-rows are (o*4+n)-ordered -> float4 per (pos,o).
__global__ __launch_bounds__(256) void attn_kernel() {
    __shared__ __align__(16) float  as[3][10][64];
    __shared__ __align__(16) float4 us[3][10][64];     // [pos][o][n in float4]
    __shared__ __align__(16) float  A_s[2][64][12];
    const int tid = threadIdx.x;
    const int sub = tid >> 7;
    const int t   = tid & 127;
    const int P0  = blockIdx.x * 8;
    const int b   = P0 >> 12;
    const int hw0 = P0 & 4095;
    const int h = hw0 >> 6, w0 = hw0 & 63;

    for (int idx = tid; idx < 2400; idx += 256) {
        int pos = idx / 80;
        int r4  = idx - pos * 80;
        int rr = pos / 10, cl = pos - rr * 10;
        int hh = h + rr - 1;
        int ww = w0 + cl - 1;
        float4 v = make_float4(0.f, 0.f, 0.f, 0.f);
        if ((unsigned)hh < 64u && (unsigned)ww < 64u)
            v = ((const float4*)(g_G + (size_t)((b << 12) + (hh << 6) + ww) * RGP))[r4];
        if (r4 < 16) {
            int r = r4 << 2;
            as[rr][cl][r] = v.x; as[rr][cl][r + 1] = v.y;
            as[rr][cl][r + 2] = v.z; as[rr][cl][r + 3] = v.w;
        } else {
            us[rr][cl][r4 - 16] = v;   // float4 = u[n=0..3] for o = r4-16
        }
    }
    __syncthreads();

    const int o  = t & 63;
    const int qb = t >> 6;

    for (int pp = 0; pp < 4; pp++) {
        const int px = pp * 2 + sub;
        if (t < 64) {
            float vals[9];
            float m = -1e30f;
            #pragma unroll
            for (int r = 0; r < 3; r++)
                #pragma unroll
                for (int j = 0; j < 3; j++) {
                    float vv = as[r][px + j][t];
                    vals[r * 3 + j] = vv;
                    m = fmaxf(m, vv);
                }
            float e[9], s = 0.f;
            #pragma unroll
            for (int l = 0; l < 9; l++) { e[l] = __expf(vals[l] - m); s += e[l]; }
            float inv = 1.f / s;
            #pragma unroll
            for (int l = 0; l < 9; l++) A_s[sub][t][l] = e[l] * inv;
        }
        __syncthreads();

        // hoist window u (all 4 heads packed per float4) into registers
        float4 uv[9];
        #pragma unroll
        for (int r = 0; r < 3; r++)
            #pragma unroll
            for (int j = 0; j < 3; j++)
                uv[r * 3 + j] = us[r][px + j][o];

        const size_t base = (size_t)(P0 + px) * YC;
        #pragma unroll
        for (int ii = 0; ii < 8; ii++) {
            int q = qb + (ii << 1);
            const float* A0 = A_s[sub][q];
            const float* A1 = A_s[sub][16 + q];
            const float* A2 = A_s[sub][32 + q];
            const float* A3 = A_s[sub][48 + q];
            float acc = 0.f;
            #pragma unroll
            for (int l = 0; l < 9; l++) {
                float4 u4 = uv[l];
                acc += A0[l] * u4.x + A1[l] * u4.y + A2[l] * u4.z + A3[l] * u4.w;
            }
            g_Yf[base + (q << 6) + o] = __float2half(acc);
        }
        __syncthreads();
    }
}

// ---------------- launcher ---------------------------------------------------
extern "C" void kernel_launch(void* const* d_in, const int* in_sizes, int n_in,
                              void* d_out, int out_size) {
    const float* x      = (const float*)d_in[0];
    const float* kv_w   = (const float*)d_in[1];
    const float* dot_w  = (const float*)d_in[2];
    const float* head_w = (const float*)d_in[3];
    const float* head_b = (const float*)d_in[4];
    const float* q_w    = (const float*)d_in[5];
    const float* q_b    = (const float*)d_in[6];
    float* out = (float*)d_out;

    cudaFuncSetAttribute(gemm_mma<256,  false>, cudaFuncAttributeMaxDynamicSharedMemorySize, SMEM_BYTES);
    cudaFuncSetAttribute(gemm_mma<1024, true >, cudaFuncAttributeMaxDynamicSharedMemorySize, SMEM_BYTES);

    precompute_kernel<<<RGP, CC>>>(kv_w, dot_w, head_w);
    zb_kernel<<<CC, 256>>>(q_w, head_b, q_b);
    convert_qw<<<(CC * YC + 511) / 512, 512>>>(q_w);
    transpose_half_x<<<dim3(HWP / 32, CC / 32, 4), dim3(32, 8)>>>(x);

    __half *wch, *wcl, *xt, *qwh, *qwl, *yf;
    cudaGetSymbolAddress((void**)&wch, g_Wch);
    cudaGetSymbolAddress((void**)&wcl, g_Wcl);
    cudaGetSymbolAddress((void**)&xt, g_xt);
    cudaGetSymbolAddress((void**)&qwh, g_qwh);
    cudaGetSymbolAddress((void**)&qwl, g_qwl);
    cudaGetSymbolAddress((void**)&yf, g_Yf);

    gemm_mma<256, false><<<dim3(NP / 128, 3), 256, SMEM_BYTES>>>(wch, wcl, xt, nullptr);
    attn_kernel<<<NP / 8, 256>>>();
    gemm_mma<1024, true><<<dim3(NP / 128, 2), 256, SMEM_BYTES>>>(qwh, qwl, yf, out);
}